// round 1
// baseline (speedup 1.0000x reference)
#include <cuda_runtime.h>
#include <math.h>

#define NP 100000
#define NA 50000
#define NEDGE 250000
#define AGG_CAP 64

// ---------------- scratch (static device globals; no allocation) ----------------
__device__ float g_xp[NP*128];
__device__ float g_xa[NA*128];
__device__ float g_qp[NP*128];
__device__ float g_qa[NA*128];
__device__ float g_k0[NA*128];
__device__ float g_v0[NA*128];
__device__ float g_k1[NP*128];
__device__ float g_v1[NP*128];
__device__ float g_k2[NP*128];
__device__ float g_v2[NP*128];
__device__ float g_aggp[NP*128];
__device__ float g_agga[NA*128];
__device__ float g_weff[12*16512];     // 12 x (128*128 weight + 128 bias)
__device__ int   g_deg[3*NP];
__device__ int   g_off[3*(NP+1)];
__device__ int   g_cur[3*NP];
__device__ int   g_eid[3*NEDGE];
__device__ int   g_part[3*128];

__device__ __forceinline__ float gelu_f(float x){
    return 0.5f*x*(1.0f + erff(x*0.70710678118654752f));
}

// ---------------- generic [N,128]x[128,128] GEMM ----------------
// mode bit0: gelu(inScale * x) applied to input
// mode bit1: blend epilogue: y = g*(acc+b) + (1-g)*Xold, g = sigmoid(*skipPtr)
__global__ void gemm128_kernel(const float* __restrict__ X, const float* __restrict__ W,
                               const float* __restrict__ B, float* __restrict__ Y,
                               const float* __restrict__ Xold, const float* __restrict__ skipPtr,
                               int N, int mode, float inScale)
{
    extern __shared__ float sm[];
    float* Wsm = sm;            // 128*128
    float* Xsm = sm + 16384;    // 64*128
    const int tid = threadIdx.x;
    const int bRow = blockIdx.x * 64;

    {
        const float4* W4 = (const float4*)W;
        float4* Ws4 = (float4*)Wsm;
        #pragma unroll
        for (int i = 0; i < 16; i++) Ws4[tid + i*256] = W4[tid + i*256];
    }
    {
        float4* Xs4 = (float4*)Xsm;
        #pragma unroll
        for (int i = 0; i < 8; i++){
            int idx = tid + i*256;
            int r = idx >> 5, c4 = idx & 31;
            int gr = bRow + r;
            float4 v = make_float4(0.f,0.f,0.f,0.f);
            if (gr < N) v = ((const float4*)X)[(size_t)gr*32 + c4];
            if (mode & 1){
                v.x = gelu_f(v.x*inScale);
                v.y = gelu_f(v.y*inScale);
                v.z = gelu_f(v.z*inScale);
                v.w = gelu_f(v.w*inScale);
            }
            Xs4[idx] = v;
        }
    }
    __syncthreads();

    const int cg = tid & 15, rg = tid >> 4;
    const int c0 = cg*8, r0 = rg*4;
    float acc[4][8];
    #pragma unroll
    for (int i=0;i<4;i++)
        #pragma unroll
        for (int j=0;j<8;j++) acc[i][j]=0.f;

    #pragma unroll 4
    for (int k=0;k<128;k++){
        float4 w0 = *(const float4*)(Wsm + k*128 + c0);
        float4 w1 = *(const float4*)(Wsm + k*128 + c0 + 4);
        #pragma unroll
        for (int i=0;i<4;i++){
            float xv = Xsm[(r0+i)*128 + k];
            acc[i][0] += xv*w0.x; acc[i][1] += xv*w0.y;
            acc[i][2] += xv*w0.z; acc[i][3] += xv*w0.w;
            acc[i][4] += xv*w1.x; acc[i][5] += xv*w1.y;
            acc[i][6] += xv*w1.z; acc[i][7] += xv*w1.w;
        }
    }

    float gate = 1.f, og = 0.f;
    if (mode & 2){ gate = 1.f/(1.f + expf(-skipPtr[0])); og = 1.f - gate; }
    float4 b0 = *(const float4*)(B + c0);
    float4 b1 = *(const float4*)(B + c0 + 4);
    #pragma unroll
    for (int i=0;i<4;i++){
        int gr = bRow + r0 + i;
        if (gr >= N) continue;
        float o[8];
        o[0]=acc[i][0]+b0.x; o[1]=acc[i][1]+b0.y; o[2]=acc[i][2]+b0.z; o[3]=acc[i][3]+b0.w;
        o[4]=acc[i][4]+b1.x; o[5]=acc[i][5]+b1.y; o[6]=acc[i][6]+b1.z; o[7]=acc[i][7]+b1.w;
        if (mode & 2){
            const float* xo = Xold + (size_t)gr*128 + c0;
            #pragma unroll
            for (int j=0;j<8;j++) o[j] = gate*o[j] + og*xo[j];
        }
        float4* y4 = (float4*)(Y + (size_t)gr*128 + c0);
        y4[0] = make_float4(o[0],o[1],o[2],o[3]);
        y4[1] = make_float4(o[4],o[5],o[6],o[7]);
    }
}

// ---------------- effective relation weights ----------------
// Weff[:, h*32+j] = sum_d W[:, h*32+d] * R[h,d,j];  bias likewise.
__global__ void weff_kernel(const float* __restrict__ k_w, const float* __restrict__ k_b,
                            const float* __restrict__ v_w, const float* __restrict__ v_b,
                            const float* __restrict__ a_rel, const float* __restrict__ m_rel)
{
    int b = blockIdx.x;                 // 0..11 = l*6 + e*2 + kv
    int l = b / 6, e = (b % 6) / 2, kv = b & 1;
    int s = (e == 0) ? 1 : 0;           // EDGE_NTYPES src: e0=author, e1/e2=paper
    const float* W  = (kv ? v_w : k_w) + (size_t)(l*2+s)*16384;
    const float* Bi = (kv ? v_b : k_b) + (l*2+s)*128;
    const float* R  = (kv ? m_rel : a_rel) + (size_t)(l*3+e)*4096;
    float* dst = g_weff + (size_t)b*16512;

    __shared__ float Rs[4096];
    for (int i = threadIdx.x; i < 4096; i += 128) Rs[i] = R[i];
    __syncthreads();

    int jc = threadIdx.x;
    int h = jc >> 5, j = jc & 31;
    const float* Rh = Rs + h*1024 + j;
    for (int i = 0; i < 128; i++){
        float acc = 0.f;
        #pragma unroll
        for (int d = 0; d < 32; d++) acc += W[i*128 + h*32 + d] * Rh[d*32];
        dst[i*128 + jc] = acc;
    }
    float accb = 0.f;
    #pragma unroll
    for (int d = 0; d < 32; d++) accb += Bi[h*32 + d] * Rh[d*32];
    dst[16384 + jc] = accb;
}

// ---------------- CSR build ----------------
__global__ void zero_int_kernel(int* __restrict__ p, int n){
    int i = blockIdx.x*blockDim.x + threadIdx.x;
    if (i < n) p[i] = 0;
}
__global__ void hist_kernel(const int* __restrict__ dst, int* __restrict__ deg, int E){
    int i = blockIdx.x*blockDim.x + threadIdx.x;
    if (i < E) atomicAdd(&deg[dst[i]], 1);
}
__global__ void partial_kernel(const int* __restrict__ deg, int* __restrict__ part, int n){
    __shared__ int s[256];
    int tid = threadIdx.x;
    int base = blockIdx.x*1024 + tid*4;
    int sum = 0;
    #pragma unroll
    for (int j = 0; j < 4; j++) if (base + j < n) sum += deg[base + j];
    s[tid] = sum; __syncthreads();
    for (int d = 128; d > 0; d >>= 1){
        if (tid < d) s[tid] += s[tid + d];
        __syncthreads();
    }
    if (tid == 0) part[blockIdx.x] = s[0];
}
__global__ void scan_part_kernel(int* __restrict__ part, int nb){
    if (threadIdx.x == 0 && blockIdx.x == 0){
        int acc = 0;
        for (int i = 0; i < nb; i++){ int v = part[i]; part[i] = acc; acc += v; }
    }
}
__global__ void offsets_kernel(const int* __restrict__ deg, const int* __restrict__ part,
                               int* __restrict__ off, int* __restrict__ cur, int n, int E){
    __shared__ int s[256];
    int tid = threadIdx.x;
    int base = blockIdx.x*1024 + tid*4;
    int v[4];
    #pragma unroll
    for (int j = 0; j < 4; j++) v[j] = (base + j < n) ? deg[base + j] : 0;
    int tsum = v[0]+v[1]+v[2]+v[3];
    s[tid] = tsum; __syncthreads();
    for (int d = 1; d < 256; d <<= 1){
        int t = (tid >= d) ? s[tid - d] : 0;
        __syncthreads();
        s[tid] += t;
        __syncthreads();
    }
    int run = s[tid] - tsum + part[blockIdx.x];
    #pragma unroll
    for (int j = 0; j < 4; j++){
        if (base + j < n){ off[base + j] = run; cur[base + j] = run; }
        run += v[j];
    }
    if (blockIdx.x == 0 && tid == 0) off[n] = E;
}
__global__ void scatter_kernel(const int* __restrict__ dst, int* __restrict__ cur,
                               int* __restrict__ eid, int E){
    int i = blockIdx.x*blockDim.x + threadIdx.x;
    if (i < E){
        int pos = atomicAdd(&cur[dst[i]], 1);
        eid[pos] = i;
    }
}

// ---------------- attention aggregation (warp per destination) ----------------
__global__ void aggregate_kernel(const int* __restrict__ off, const int* __restrict__ eid,
                                 const int* __restrict__ srcArr,
                                 const float* __restrict__ Q, const float* __restrict__ K,
                                 const float* __restrict__ V, const float* __restrict__ prel,
                                 float* __restrict__ OUT, int Nd)
{
    __shared__ float exbuf[8][AGG_CAP][4];
    int wl = threadIdx.x >> 5;
    int lane = threadIdx.x & 31;
    int dstid = blockIdx.x*8 + wl;
    if (dstid >= Nd) return;
    int e0 = off[dstid], e1 = off[dstid+1];
    int h = lane >> 3;
    float ph = prel[h] * 0.17677669529663687f;   // p_rel * 1/sqrt(32)
    float4 q4 = ((const float4*)Q)[(size_t)dstid*32 + lane];
    float den = 0.f;
    for (int e = e0; e < e1; e++){
        int s = srcArr[eid[e]];
        float4 k4 = ((const float4*)K)[(size_t)s*32 + lane];
        float p = q4.x*k4.x + q4.y*k4.y + q4.z*k4.z + q4.w*k4.w;
        p += __shfl_xor_sync(0xffffffffu, p, 1);
        p += __shfl_xor_sync(0xffffffffu, p, 2);
        p += __shfl_xor_sync(0xffffffffu, p, 4);
        float ex = expf(p * ph);
        den += ex;
        int el = e - e0;
        if (el < AGG_CAP && (lane & 7) == 0) exbuf[wl][el][h] = ex;
    }
    float inv = 1.f/(den + 1e-16f);
    __syncwarp();
    float4 acc = ((float4*)OUT)[(size_t)dstid*32 + lane];
    for (int e = e0; e < e1; e++){
        int el = e - e0;
        int s = srcArr[eid[e]];
        float ex;
        if (el < AGG_CAP) ex = exbuf[wl][el][h];
        else {
            float4 k4 = ((const float4*)K)[(size_t)s*32 + lane];
            float p = q4.x*k4.x + q4.y*k4.y + q4.z*k4.z + q4.w*k4.w;
            p += __shfl_xor_sync(0xffffffffu, p, 1);
            p += __shfl_xor_sync(0xffffffffu, p, 2);
            p += __shfl_xor_sync(0xffffffffu, p, 4);
            ex = expf(p * ph);
        }
        float w = ex * inv;
        float4 v4 = ((const float4*)V)[(size_t)s*32 + lane];
        acc.x += v4.x*w; acc.y += v4.y*w; acc.z += v4.z*w; acc.w += v4.w*w;
    }
    ((float4*)OUT)[(size_t)dstid*32 + lane] = acc;
}

// ---------------- misc ----------------
__global__ void gather_embed_kernel(const float* __restrict__ tab, const int* __restrict__ idx,
                                    float* __restrict__ out, int n){
    int i = blockIdx.x*blockDim.x + threadIdx.x;
    if (i >= n*32) return;
    int node = i >> 5, c = i & 31;
    int src = idx[node];
    ((float4*)out)[(size_t)node*32 + c] = ((const float4*)tab)[(size_t)src*32 + c];
}
__global__ void zero_float_kernel(float4* __restrict__ p, int n4){
    int i = blockIdx.x*blockDim.x + threadIdx.x;
    if (i < n4) p[i] = make_float4(0.f,0.f,0.f,0.f);
}
__global__ void copy_out_kernel(const float* __restrict__ xp, const float* __restrict__ xa,
                                float4* __restrict__ out){
    int i = blockIdx.x*blockDim.x + threadIdx.x;
    const int n1 = 50000*32, n2 = 25000*32;
    if (i < n1) out[i] = ((const float4*)xp)[i];
    else if (i < n1 + n2) out[i] = ((const float4*)xa)[i - n1];
}

// ---------------- launch ----------------
extern "C" void kernel_launch(void* const* d_in, const int* in_sizes, int n_in,
                              void* d_out, int out_size)
{
    const float* x_paper     = (const float*)d_in[0];
    const int*   author_idx  = (const int*)  d_in[1];
    const float* embed_table = (const float*)d_in[2];
    const float* lin_w       = (const float*)d_in[3];
    const float* lin_b       = (const float*)d_in[4];
    const float* k_w         = (const float*)d_in[5];
    const float* k_b         = (const float*)d_in[6];
    const float* q_w         = (const float*)d_in[7];
    const float* q_b         = (const float*)d_in[8];
    const float* v_w         = (const float*)d_in[9];
    const float* v_b         = (const float*)d_in[10];
    const float* a_rel       = (const float*)d_in[11];
    const float* m_rel       = (const float*)d_in[12];
    const float* p_rel       = (const float*)d_in[13];
    const float* skip        = (const float*)d_in[14];
    const float* a_w         = (const float*)d_in[15];
    const float* a_b         = (const float*)d_in[16];
    const int*   w_src       = (const int*)  d_in[17];
    const int*   w_dst       = (const int*)  d_in[18];
    const int*   r_src       = (const int*)  d_in[19];
    const int*   r_dst       = (const int*)  d_in[20];
    const int*   c_src       = (const int*)  d_in[21];
    const int*   c_dst       = (const int*)  d_in[22];
    float* out = (float*)d_out;

    float *xp,*xa,*qp,*qa,*k0,*v0,*k1,*v1,*k2,*v2,*aggp,*agga,*weff;
    int *deg,*off,*cur,*eid,*part;
    cudaGetSymbolAddress((void**)&xp,   g_xp);
    cudaGetSymbolAddress((void**)&xa,   g_xa);
    cudaGetSymbolAddress((void**)&qp,   g_qp);
    cudaGetSymbolAddress((void**)&qa,   g_qa);
    cudaGetSymbolAddress((void**)&k0,   g_k0);
    cudaGetSymbolAddress((void**)&v0,   g_v0);
    cudaGetSymbolAddress((void**)&k1,   g_k1);
    cudaGetSymbolAddress((void**)&v1,   g_v1);
    cudaGetSymbolAddress((void**)&k2,   g_k2);
    cudaGetSymbolAddress((void**)&v2,   g_v2);
    cudaGetSymbolAddress((void**)&aggp, g_aggp);
    cudaGetSymbolAddress((void**)&agga, g_agga);
    cudaGetSymbolAddress((void**)&weff, g_weff);
    cudaGetSymbolAddress((void**)&deg,  g_deg);
    cudaGetSymbolAddress((void**)&off,  g_off);
    cudaGetSymbolAddress((void**)&cur,  g_cur);
    cudaGetSymbolAddress((void**)&eid,  g_eid);
    cudaGetSymbolAddress((void**)&part, g_part);

    cudaFuncSetAttribute(gemm128_kernel, cudaFuncAttributeMaxDynamicSharedMemorySize, 98304);

    // CSR build per edge type (fixed across layers)
    const int* dsts[3] = { w_dst, r_dst, c_dst };
    const int  Nds[3]  = { NP, NA, NP };
    for (int t = 0; t < 3; t++){
        int n = Nds[t];
        int* degT  = deg  + t*NP;
        int* offT  = off  + t*(NP+1);
        int* curT  = cur  + t*NP;
        int* eidT  = eid  + t*NEDGE;
        int* partT = part + t*128;
        int nb = (n + 1023)/1024;
        zero_int_kernel<<<(n+255)/256,256>>>(degT, n);
        hist_kernel<<<(NEDGE+255)/256,256>>>(dsts[t], degT, NEDGE);
        partial_kernel<<<nb,256>>>(degT, partT, n);
        scan_part_kernel<<<1,32>>>(partT, nb);
        offsets_kernel<<<nb,256>>>(degT, partT, offT, curT, n, NEDGE);
        scatter_kernel<<<(NEDGE+255)/256,256>>>(dsts[t], curT, eidT, NEDGE);
    }

    // relation-folded k/v weights
    weff_kernel<<<12,128>>>(k_w, k_b, v_w, v_b, a_rel, m_rel);

    // input projections
    gemm128_kernel<<<(NP+63)/64,256,98304>>>(x_paper, lin_w, lin_b, xp, nullptr, nullptr, NP, 0, 1.f);
    gather_embed_kernel<<<(NA*32+255)/256,256>>>(embed_table, author_idx, xa, NA);

    for (int l = 0; l < 2; l++){
        gemm128_kernel<<<(NP+63)/64,256,98304>>>(xp, q_w + (size_t)(l*2+0)*16384, q_b + (l*2+0)*128, qp, nullptr, nullptr, NP, 0, 1.f);
        gemm128_kernel<<<(NA+63)/64,256,98304>>>(xa, q_w + (size_t)(l*2+1)*16384, q_b + (l*2+1)*128, qa, nullptr, nullptr, NA, 0, 1.f);

        const float* we;
        we = weff + (size_t)((l*3+0)*2+0)*16512;
        gemm128_kernel<<<(NA+63)/64,256,98304>>>(xa, we, we+16384, k0, nullptr, nullptr, NA, 0, 1.f);
        we = weff + (size_t)((l*3+0)*2+1)*16512;
        gemm128_kernel<<<(NA+63)/64,256,98304>>>(xa, we, we+16384, v0, nullptr, nullptr, NA, 0, 1.f);
        we = weff + (size_t)((l*3+1)*2+0)*16512;
        gemm128_kernel<<<(NP+63)/64,256,98304>>>(xp, we, we+16384, k1, nullptr, nullptr, NP, 0, 1.f);
        we = weff + (size_t)((l*3+1)*2+1)*16512;
        gemm128_kernel<<<(NP+63)/64,256,98304>>>(xp, we, we+16384, v1, nullptr, nullptr, NP, 0, 1.f);
        we = weff + (size_t)((l*3+2)*2+0)*16512;
        gemm128_kernel<<<(NP+63)/64,256,98304>>>(xp, we, we+16384, k2, nullptr, nullptr, NP, 0, 1.f);
        we = weff + (size_t)((l*3+2)*2+1)*16512;
        gemm128_kernel<<<(NP+63)/64,256,98304>>>(xp, we, we+16384, v2, nullptr, nullptr, NP, 0, 1.f);

        zero_float_kernel<<<(NP*32+255)/256,256>>>((float4*)aggp, NP*32);
        zero_float_kernel<<<(NA*32+255)/256,256>>>((float4*)agga, NA*32);

        // e0: author->paper ; e2: paper->paper (both accumulate into aggp) ; e1: paper->author
        aggregate_kernel<<<(NP+7)/8,256>>>(off + 0*(NP+1), eid + 0*NEDGE, w_src, qp, k0, v0, p_rel + (l*3+0)*4, aggp, NP);
        aggregate_kernel<<<(NP+7)/8,256>>>(off + 2*(NP+1), eid + 2*NEDGE, c_src, qp, k2, v2, p_rel + (l*3+2)*4, aggp, NP);
        aggregate_kernel<<<(NA+7)/8,256>>>(off + 1*(NP+1), eid + 1*NEDGE, r_src, qa, k1, v1, p_rel + (l*3+1)*4, agga, NA);

        // update: y = sigmoid(skip)*(gelu(mean)@a_w + a_b) + (1-sigmoid(skip))*x
        gemm128_kernel<<<(NP+63)/64,256,98304>>>(aggp, a_w + (size_t)(l*2+0)*16384, a_b + (l*2+0)*128, xp, xp, skip + l*2+0, NP, 3, 0.5f);
        gemm128_kernel<<<(NA+63)/64,256,98304>>>(agga, a_w + (size_t)(l*2+1)*16384, a_b + (l*2+1)*128, xa, xa, skip + l*2+1, NA, 3, 1.0f);
    }

    copy_out_kernel<<<(2400000+255)/256,256>>>(xp, xa, (float4*)out);
}

// round 2
// speedup vs baseline: 1.1783x; 1.1783x over previous
#include <cuda_runtime.h>
#include <math.h>
#include <mma.h>

using namespace nvcuda;

#define NP 100000
#define NA 50000
#define NEDGE 250000
#define AGG_CAP 64

#define XS_STRIDE 68
#define WS_STRIDE 132
#define SMEM_FLOATS (128*XS_STRIDE + 64*WS_STRIDE)   // 17152 floats = 68608 B (>= 128*WS_STRIDE for out staging)

// ---------------- scratch (static device globals; no allocation) ----------------
__device__ float g_xp[NP*128];
__device__ float g_xa[NA*128];
__device__ float g_qp[NP*128];
__device__ float g_qa[NA*128];
__device__ float g_k0[NA*128];
__device__ float g_v0[NA*128];
__device__ float g_k1[NP*128];
__device__ float g_v1[NP*128];
__device__ float g_k2[NP*128];
__device__ float g_v2[NP*128];
__device__ float g_aggp[NP*128];
__device__ float g_agga[NA*128];
__device__ float g_weff[12*16512];     // 12 x (128*128 weight + 128 bias)
__device__ int   g_deg[3*NP];
__device__ int   g_off[3*(NP+1)];
__device__ int   g_cur[3*NP];
__device__ int   g_eid[3*NEDGE];
__device__ int   g_part[3*128];

__device__ __forceinline__ float gelu_f(float x){
    return 0.5f*x*(1.0f + erff(x*0.70710678118654752f));
}

// ---------------- tf32 tensor-core GEMM: [N,128] x [128,128] ----------------
// mode bit0: gelu(inScale * x) applied to input
// mode bit1: blend epilogue: y = g*(acc+b) + (1-g)*Xold, g = sigmoid(*skipPtr)
__global__ void gemm128_tc(const float* __restrict__ X, const float* __restrict__ W,
                           const float* __restrict__ B, float* __restrict__ Y,
                           const float* __restrict__ Xold, const float* __restrict__ skipPtr,
                           int N, int mode, float inScale)
{
    extern __shared__ float sm[];
    float* Xs = sm;                       // 128 x XS_STRIDE (uses 64 cols)
    float* Ws = sm + 128*XS_STRIDE;       // 64  x WS_STRIDE (uses 128 cols)
    const int tid  = threadIdx.x;
    const int warp = tid >> 5;
    const int bRow = blockIdx.x * 128;

    wmma::fragment<wmma::accumulator, 16,16,8, float> acc[8];
    #pragma unroll
    for (int c = 0; c < 8; c++) wmma::fill_fragment(acc[c], 0.f);

    #pragma unroll
    for (int kk = 0; kk < 128; kk += 64){
        // X chunk: rows [bRow, bRow+128), cols [kk, kk+64)
        #pragma unroll
        for (int i = 0; i < 8; i++){
            int idx = tid + i*256;            // 2048 float4s
            int r = idx >> 4;                 // 16 float4 per row
            int c4 = idx & 15;
            int gr = bRow + r;
            float4 v = make_float4(0.f,0.f,0.f,0.f);
            if (gr < N) v = ((const float4*)X)[(size_t)gr*32 + (kk>>2) + c4];
            if (mode & 1){
                v.x = gelu_f(v.x*inScale); v.y = gelu_f(v.y*inScale);
                v.z = gelu_f(v.z*inScale); v.w = gelu_f(v.w*inScale);
            }
            float* d = Xs + r*XS_STRIDE + c4*4;
            d[0] = wmma::__float_to_tf32(v.x);
            d[1] = wmma::__float_to_tf32(v.y);
            d[2] = wmma::__float_to_tf32(v.z);
            d[3] = wmma::__float_to_tf32(v.w);
        }
        // W chunk: rows [kk, kk+64), cols [0,128)
        #pragma unroll
        for (int i = 0; i < 8; i++){
            int idx = tid + i*256;            // 2048 float4s
            int r = idx >> 5;                 // 32 float4 per row
            int c4 = idx & 31;
            float4 v = ((const float4*)W)[(size_t)(kk + r)*32 + c4];
            float* d = Ws + r*WS_STRIDE + c4*4;
            d[0] = wmma::__float_to_tf32(v.x);
            d[1] = wmma::__float_to_tf32(v.y);
            d[2] = wmma::__float_to_tf32(v.z);
            d[3] = wmma::__float_to_tf32(v.w);
        }
        __syncthreads();

        #pragma unroll
        for (int ks = 0; ks < 8; ks++){
            wmma::fragment<wmma::matrix_a, 16,16,8, wmma::precision::tf32, wmma::row_major> a;
            wmma::load_matrix_sync(a, Xs + (warp*16)*XS_STRIDE + ks*8, XS_STRIDE);
            #pragma unroll
            for (int c = 0; c < 8; c++){
                wmma::fragment<wmma::matrix_b, 16,16,8, wmma::precision::tf32, wmma::row_major> b;
                wmma::load_matrix_sync(b, Ws + (ks*8)*WS_STRIDE + c*16, WS_STRIDE);
                wmma::mma_sync(acc[c], a, b, acc[c]);
            }
        }
        __syncthreads();
    }

    // stage accumulators to smem (reuse Xs/Ws region)
    float* OutS = sm;                     // 128 x WS_STRIDE
    #pragma unroll
    for (int c = 0; c < 8; c++)
        wmma::store_matrix_sync(OutS + (warp*16)*WS_STRIDE + c*16, acc[c], WS_STRIDE, wmma::mem_row_major);
    __syncthreads();

    float gate = 1.f, og = 0.f;
    if (mode & 2){ gate = 1.f/(1.f + expf(-skipPtr[0])); og = 1.f - gate; }
    #pragma unroll
    for (int i = 0; i < 16; i++){
        int idx = tid + i*256;            // 4096 float4s
        int r = idx >> 5;
        int c4 = idx & 31;
        int gr = bRow + r;
        if (gr >= N) continue;
        const float* o = OutS + r*WS_STRIDE + c4*4;
        float4 bv = ((const float4*)B)[c4];
        float4 res;
        res.x = o[0] + bv.x; res.y = o[1] + bv.y;
        res.z = o[2] + bv.z; res.w = o[3] + bv.w;
        if (mode & 2){
            float4 xo = ((const float4*)Xold)[(size_t)gr*32 + c4];
            res.x = gate*res.x + og*xo.x; res.y = gate*res.y + og*xo.y;
            res.z = gate*res.z + og*xo.z; res.w = gate*res.w + og*xo.w;
        }
        ((float4*)Y)[(size_t)gr*32 + c4] = res;
    }
}

// ---------------- effective relation weights ----------------
// Weff[:, h*32+j] = sum_d W[:, h*32+d] * R[h,d,j];  bias likewise.
__global__ void weff_kernel(const float* __restrict__ k_w, const float* __restrict__ k_b,
                            const float* __restrict__ v_w, const float* __restrict__ v_b,
                            const float* __restrict__ a_rel, const float* __restrict__ m_rel)
{
    int b = blockIdx.x;                 // 0..11 = l*6 + e*2 + kv
    int l = b / 6, e = (b % 6) / 2, kv = b & 1;
    int s = (e == 0) ? 1 : 0;           // EDGE_NTYPES src: e0=author, e1/e2=paper
    const float* W  = (kv ? v_w : k_w) + (size_t)(l*2+s)*16384;
    const float* Bi = (kv ? v_b : k_b) + (l*2+s)*128;
    const float* R  = (kv ? m_rel : a_rel) + (size_t)(l*3+e)*4096;
    float* dst = g_weff + (size_t)b*16512;

    __shared__ float Rs[4096];
    for (int i = threadIdx.x; i < 4096; i += 128) Rs[i] = R[i];
    __syncthreads();

    int jc = threadIdx.x;
    int h = jc >> 5, j = jc & 31;
    const float* Rh = Rs + h*1024 + j;
    int i0 = blockIdx.y * 32;
    for (int i = i0; i < i0 + 32; i++){
        float acc = 0.f;
        #pragma unroll
        for (int d = 0; d < 32; d++) acc += W[i*128 + h*32 + d] * Rh[d*32];
        dst[i*128 + jc] = acc;
    }
    if (blockIdx.y == 0){
        float accb = 0.f;
        #pragma unroll
        for (int d = 0; d < 32; d++) accb += Bi[h*32 + d] * Rh[d*32];
        dst[16384 + jc] = accb;
    }
}

// ---------------- CSR build ----------------
__global__ void zero_int_kernel(int* __restrict__ p, int n){
    int i = blockIdx.x*blockDim.x + threadIdx.x;
    if (i < n) p[i] = 0;
}
__global__ void hist_kernel(const int* __restrict__ dst, int* __restrict__ deg, int E){
    int i = blockIdx.x*blockDim.x + threadIdx.x;
    if (i < E) atomicAdd(&deg[dst[i]], 1);
}
__global__ void partial_kernel(const int* __restrict__ deg, int* __restrict__ part, int n){
    __shared__ int s[256];
    int tid = threadIdx.x;
    int base = blockIdx.x*1024 + tid*4;
    int sum = 0;
    #pragma unroll
    for (int j = 0; j < 4; j++) if (base + j < n) sum += deg[base + j];
    s[tid] = sum; __syncthreads();
    for (int d = 128; d > 0; d >>= 1){
        if (tid < d) s[tid] += s[tid + d];
        __syncthreads();
    }
    if (tid == 0) part[blockIdx.x] = s[0];
}
__global__ void scan_part_kernel(int* __restrict__ part, int nb){
    if (threadIdx.x == 0 && blockIdx.x == 0){
        int acc = 0;
        for (int i = 0; i < nb; i++){ int v = part[i]; part[i] = acc; acc += v; }
    }
}
__global__ void offsets_kernel(const int* __restrict__ deg, const int* __restrict__ part,
                               int* __restrict__ off, int* __restrict__ cur, int n, int E){
    __shared__ int s[256];
    int tid = threadIdx.x;
    int base = blockIdx.x*1024 + tid*4;
    int v[4];
    #pragma unroll
    for (int j = 0; j < 4; j++) v[j] = (base + j < n) ? deg[base + j] : 0;
    int tsum = v[0]+v[1]+v[2]+v[3];
    s[tid] = tsum; __syncthreads();
    for (int d = 1; d < 256; d <<= 1){
        int t = (tid >= d) ? s[tid - d] : 0;
        __syncthreads();
        s[tid] += t;
        __syncthreads();
    }
    int run = s[tid] - tsum + part[blockIdx.x];
    #pragma unroll
    for (int j = 0; j < 4; j++){
        if (base + j < n){ off[base + j] = run; cur[base + j] = run; }
        run += v[j];
    }
    if (blockIdx.x == 0 && tid == 0) off[n] = E;
}
__global__ void scatter_kernel(const int* __restrict__ dst, int* __restrict__ cur,
                               int* __restrict__ eid, int E){
    int i = blockIdx.x*blockDim.x + threadIdx.x;
    if (i < E){
        int pos = atomicAdd(&cur[dst[i]], 1);
        eid[pos] = i;
    }
}

// ---------------- attention aggregation (warp per destination) ----------------
__global__ void aggregate_kernel(const int* __restrict__ off, const int* __restrict__ eid,
                                 const int* __restrict__ srcArr,
                                 const float* __restrict__ Q, const float* __restrict__ K,
                                 const float* __restrict__ V, const float* __restrict__ prel,
                                 float* __restrict__ OUT, int Nd)
{
    __shared__ float exbuf[8][AGG_CAP][4];
    int wl = threadIdx.x >> 5;
    int lane = threadIdx.x & 31;
    int dstid = blockIdx.x*8 + wl;
    if (dstid >= Nd) return;
    int e0 = off[dstid], e1 = off[dstid+1];
    int h = lane >> 3;
    float ph = prel[h] * 0.17677669529663687f;   // p_rel * 1/sqrt(32)
    float4 q4 = ((const float4*)Q)[(size_t)dstid*32 + lane];
    float den = 0.f;
    for (int e = e0; e < e1; e++){
        int s = srcArr[eid[e]];
        float4 k4 = ((const float4*)K)[(size_t)s*32 + lane];
        float p = q4.x*k4.x + q4.y*k4.y + q4.z*k4.z + q4.w*k4.w;
        p += __shfl_xor_sync(0xffffffffu, p, 1);
        p += __shfl_xor_sync(0xffffffffu, p, 2);
        p += __shfl_xor_sync(0xffffffffu, p, 4);
        float ex = expf(p * ph);
        den += ex;
        int el = e - e0;
        if (el < AGG_CAP && (lane & 7) == 0) exbuf[wl][el][h] = ex;
    }
    float inv = 1.f/(den + 1e-16f);
    __syncwarp();
    float4 acc = ((float4*)OUT)[(size_t)dstid*32 + lane];
    for (int e = e0; e < e1; e++){
        int el = e - e0;
        int s = srcArr[eid[e]];
        float ex;
        if (el < AGG_CAP) ex = exbuf[wl][el][h];
        else {
            float4 k4 = ((const float4*)K)[(size_t)s*32 + lane];
            float p = q4.x*k4.x + q4.y*k4.y + q4.z*k4.z + q4.w*k4.w;
            p += __shfl_xor_sync(0xffffffffu, p, 1);
            p += __shfl_xor_sync(0xffffffffu, p, 2);
            p += __shfl_xor_sync(0xffffffffu, p, 4);
            ex = expf(p * ph);
        }
        float w = ex * inv;
        float4 v4 = ((const float4*)V)[(size_t)s*32 + lane];
        acc.x += v4.x*w; acc.y += v4.y*w; acc.z += v4.z*w; acc.w += v4.w*w;
    }
    ((float4*)OUT)[(size_t)dstid*32 + lane] = acc;
}

// ---------------- misc ----------------
__global__ void gather_embed_kernel(const float* __restrict__ tab, const int* __restrict__ idx,
                                    float* __restrict__ out, int n){
    int i = blockIdx.x*blockDim.x + threadIdx.x;
    if (i >= n*32) return;
    int node = i >> 5, c = i & 31;
    int src = idx[node];
    ((float4*)out)[(size_t)node*32 + c] = ((const float4*)tab)[(size_t)src*32 + c];
}
__global__ void zero_float_kernel(float4* __restrict__ p, int n4){
    int i = blockIdx.x*blockDim.x + threadIdx.x;
    if (i < n4) p[i] = make_float4(0.f,0.f,0.f,0.f);
}
__global__ void copy_out_kernel(const float* __restrict__ xp, const float* __restrict__ xa,
                                float4* __restrict__ out){
    int i = blockIdx.x*blockDim.x + threadIdx.x;
    const int n1 = 50000*32, n2 = 25000*32;
    if (i < n1) out[i] = ((const float4*)xp)[i];
    else if (i < n1 + n2) out[i] = ((const float4*)xa)[i - n1];
}

// ---------------- launch ----------------
extern "C" void kernel_launch(void* const* d_in, const int* in_sizes, int n_in,
                              void* d_out, int out_size)
{
    const float* x_paper     = (const float*)d_in[0];
    const int*   author_idx  = (const int*)  d_in[1];
    const float* embed_table = (const float*)d_in[2];
    const float* lin_w       = (const float*)d_in[3];
    const float* lin_b       = (const float*)d_in[4];
    const float* k_w         = (const float*)d_in[5];
    const float* k_b         = (const float*)d_in[6];
    const float* q_w         = (const float*)d_in[7];
    const float* q_b         = (const float*)d_in[8];
    const float* v_w         = (const float*)d_in[9];
    const float* v_b         = (const float*)d_in[10];
    const float* a_rel       = (const float*)d_in[11];
    const float* m_rel       = (const float*)d_in[12];
    const float* p_rel       = (const float*)d_in[13];
    const float* skip        = (const float*)d_in[14];
    const float* a_w         = (const float*)d_in[15];
    const float* a_b         = (const float*)d_in[16];
    const int*   w_src       = (const int*)  d_in[17];
    const int*   w_dst       = (const int*)  d_in[18];
    const int*   r_src       = (const int*)  d_in[19];
    const int*   r_dst       = (const int*)  d_in[20];
    const int*   c_src       = (const int*)  d_in[21];
    const int*   c_dst       = (const int*)  d_in[22];
    float* out = (float*)d_out;

    float *xp,*xa,*qp,*qa,*k0,*v0,*k1,*v1,*k2,*v2,*aggp,*agga,*weff;
    int *deg,*off,*cur,*eid,*part;
    cudaGetSymbolAddress((void**)&xp,   g_xp);
    cudaGetSymbolAddress((void**)&xa,   g_xa);
    cudaGetSymbolAddress((void**)&qp,   g_qp);
    cudaGetSymbolAddress((void**)&qa,   g_qa);
    cudaGetSymbolAddress((void**)&k0,   g_k0);
    cudaGetSymbolAddress((void**)&v0,   g_v0);
    cudaGetSymbolAddress((void**)&k1,   g_k1);
    cudaGetSymbolAddress((void**)&v1,   g_v1);
    cudaGetSymbolAddress((void**)&k2,   g_k2);
    cudaGetSymbolAddress((void**)&v2,   g_v2);
    cudaGetSymbolAddress((void**)&aggp, g_aggp);
    cudaGetSymbolAddress((void**)&agga, g_agga);
    cudaGetSymbolAddress((void**)&weff, g_weff);
    cudaGetSymbolAddress((void**)&deg,  g_deg);
    cudaGetSymbolAddress((void**)&off,  g_off);
    cudaGetSymbolAddress((void**)&cur,  g_cur);
    cudaGetSymbolAddress((void**)&eid,  g_eid);
    cudaGetSymbolAddress((void**)&part, g_part);

    cudaFuncSetAttribute(gemm128_tc, cudaFuncAttributeMaxDynamicSharedMemorySize, SMEM_FLOATS*4);

    // CSR build per edge type (fixed across layers)
    const int* dsts[3] = { w_dst, r_dst, c_dst };
    const int  Nds[3]  = { NP, NA, NP };
    for (int t = 0; t < 3; t++){
        int n = Nds[t];
        int* degT  = deg  + t*NP;
        int* offT  = off  + t*(NP+1);
        int* curT  = cur  + t*NP;
        int* eidT  = eid  + t*NEDGE;
        int* partT = part + t*128;
        int nb = (n + 1023)/1024;
        zero_int_kernel<<<(n+255)/256,256>>>(degT, n);
        hist_kernel<<<(NEDGE+255)/256,256>>>(dsts[t], degT, NEDGE);
        partial_kernel<<<nb,256>>>(degT, partT, n);
        scan_part_kernel<<<1,32>>>(partT, nb);
        offsets_kernel<<<nb,256>>>(degT, partT, offT, curT, n, NEDGE);
        scatter_kernel<<<(NEDGE+255)/256,256>>>(dsts[t], curT, eidT, NEDGE);
    }

    // relation-folded k/v weights
    weff_kernel<<<dim3(12,4),128>>>(k_w, k_b, v_w, v_b, a_rel, m_rel);

    const int SMB = SMEM_FLOATS*4;
    const int GP = (NP+127)/128, GA = (NA+127)/128;

    // input projections
    gemm128_tc<<<GP,256,SMB>>>(x_paper, lin_w, lin_b, xp, nullptr, nullptr, NP, 0, 1.f);
    gather_embed_kernel<<<(NA*32+255)/256,256>>>(embed_table, author_idx, xa, NA);

    for (int l = 0; l < 2; l++){
        gemm128_tc<<<GP,256,SMB>>>(xp, q_w + (size_t)(l*2+0)*16384, q_b + (l*2+0)*128, qp, nullptr, nullptr, NP, 0, 1.f);
        gemm128_tc<<<GA,256,SMB>>>(xa, q_w + (size_t)(l*2+1)*16384, q_b + (l*2+1)*128, qa, nullptr, nullptr, NA, 0, 1.f);

        const float* we;
        we = weff + (size_t)((l*3+0)*2+0)*16512;
        gemm128_tc<<<GA,256,SMB>>>(xa, we, we+16384, k0, nullptr, nullptr, NA, 0, 1.f);
        we = weff + (size_t)((l*3+0)*2+1)*16512;
        gemm128_tc<<<GA,256,SMB>>>(xa, we, we+16384, v0, nullptr, nullptr, NA, 0, 1.f);
        we = weff + (size_t)((l*3+1)*2+0)*16512;
        gemm128_tc<<<GP,256,SMB>>>(xp, we, we+16384, k1, nullptr, nullptr, NP, 0, 1.f);
        we = weff + (size_t)((l*3+1)*2+1)*16512;
        gemm128_tc<<<GP,256,SMB>>>(xp, we, we+16384, v1, nullptr, nullptr, NP, 0, 1.f);
        we = weff + (size_t)((l*3+2)*2+0)*16512;
        gemm128_tc<<<GP,256,SMB>>>(xp, we, we+16384, k2, nullptr, nullptr, NP, 0, 1.f);
        we = weff + (size_t)((l*3+2)*2+1)*16512;
        gemm128_tc<<<GP,256,SMB>>>(xp, we, we+16384, v2, nullptr, nullptr, NP, 0, 1.f);

        zero_float_kernel<<<(NP*32+255)/256,256>>>((float4*)aggp, NP*32);
        zero_float_kernel<<<(NA*32+255)/256,256>>>((float4*)agga, NA*32);

        // e0: author->paper ; e2: paper->paper (both accumulate into aggp) ; e1: paper->author
        aggregate_kernel<<<(NP+7)/8,256>>>(off + 0*(NP+1), eid + 0*NEDGE, w_src, qp, k0, v0, p_rel + (l*3+0)*4, aggp, NP);
        aggregate_kernel<<<(NP+7)/8,256>>>(off + 2*(NP+1), eid + 2*NEDGE, c_src, qp, k2, v2, p_rel + (l*3+2)*4, aggp, NP);
        aggregate_kernel<<<(NA+7)/8,256>>>(off + 1*(NP+1), eid + 1*NEDGE, r_src, qa, k1, v1, p_rel + (l*3+1)*4, agga, NA);

        // update: y = sigmoid(skip)*(gelu(mean)@a_w + a_b) + (1-sigmoid(skip))*x
        gemm128_tc<<<GP,256,SMB>>>(aggp, a_w + (size_t)(l*2+0)*16384, a_b + (l*2+0)*128, xp, xp, skip + l*2+0, NP, 3, 0.5f);
        gemm128_tc<<<GA,256,SMB>>>(agga, a_w + (size_t)(l*2+1)*16384, a_b + (l*2+1)*128, xa, xa, skip + l*2+1, NA, 3, 1.0f);
    }

    copy_out_kernel<<<(2400000+255)/256,256>>>(xp, xa, (float4*)out);
}

// round 3
// speedup vs baseline: 1.4533x; 1.2333x over previous
#include <cuda_runtime.h>
#include <math.h>
#include <mma.h>

using namespace nvcuda;

#define NP 100000
#define NA 50000
#define NEDGE 250000

#define XS_STRIDE 68
#define WS_STRIDE 132
#define SMEM_FLOATS (128*XS_STRIDE + 64*WS_STRIDE)

#define WP_SZ (128*640 + 640)
#define WA_SZ (128*384 + 384)

// ---------------- scratch ----------------
__device__ float g_xp[NP*128];
__device__ float g_xa[NA*128];
__device__ float g_actp[(size_t)NP*640];   // [q k1 v1 k2 v2]
__device__ float g_acta[(size_t)NA*384];   // [q k0 v0]
__device__ float g_aggp[NP*128];
__device__ float g_agga[NA*128];
__device__ float g_wp[2*WP_SZ];
__device__ float g_wa[2*WA_SZ];
__device__ int   g_deg[3*NP];
__device__ int   g_off[3*NP+1];
__device__ int   g_cur[3*NP];
__device__ int   g_srcs[3*NEDGE];
__device__ int   g_part[512];

__device__ __forceinline__ float gelu_f(float x){
    return 0.5f*x*(1.0f + erff(x*0.70710678118654752f));
}

// ---------------- tf32 tensor-core GEMM: [N,128] x [128,Nw], col tile via blockIdx.y ----------------
// mode bit0: gelu(inScale*x) on input ; bit1: blend y = g*(acc+b)+(1-g)*Xold
__global__ void gemm128_tc(const float* __restrict__ X, const float* __restrict__ W, int ldw,
                           const float* __restrict__ B, float* __restrict__ Y, int ldy,
                           const float* __restrict__ Xold, const float* __restrict__ skipPtr,
                           int N, int mode, float inScale)
{
    extern __shared__ float sm[];
    float* Xs = sm;                       // 128 x XS_STRIDE (64 cols used)
    float* Ws = sm + 128*XS_STRIDE;       // 64  x WS_STRIDE (128 cols used)
    const int tid  = threadIdx.x;
    const int warp = tid >> 5;
    const int bRow = blockIdx.x * 128;
    const int colBase = blockIdx.y * 128;
    const int ldw4 = ldw >> 2, ldy4 = ldy >> 2, cb4 = colBase >> 2;

    wmma::fragment<wmma::accumulator, 16,16,8, float> acc[8];
    #pragma unroll
    for (int c = 0; c < 8; c++) wmma::fill_fragment(acc[c], 0.f);

    #pragma unroll
    for (int kk = 0; kk < 128; kk += 64){
        #pragma unroll
        for (int i = 0; i < 8; i++){
            int idx = tid + i*256;
            int r = idx >> 4, c4 = idx & 15;
            int gr = bRow + r;
            float4 v = make_float4(0.f,0.f,0.f,0.f);
            if (gr < N) v = ((const float4*)X)[(size_t)gr*32 + (kk>>2) + c4];
            if (mode & 1){
                v.x = gelu_f(v.x*inScale); v.y = gelu_f(v.y*inScale);
                v.z = gelu_f(v.z*inScale); v.w = gelu_f(v.w*inScale);
            }
            float* d = Xs + r*XS_STRIDE + c4*4;
            d[0] = wmma::__float_to_tf32(v.x);
            d[1] = wmma::__float_to_tf32(v.y);
            d[2] = wmma::__float_to_tf32(v.z);
            d[3] = wmma::__float_to_tf32(v.w);
        }
        #pragma unroll
        for (int i = 0; i < 8; i++){
            int idx = tid + i*256;
            int r = idx >> 5, c4 = idx & 31;
            float4 v = ((const float4*)W)[(size_t)(kk + r)*ldw4 + cb4 + c4];
            float* d = Ws + r*WS_STRIDE + c4*4;
            d[0] = wmma::__float_to_tf32(v.x);
            d[1] = wmma::__float_to_tf32(v.y);
            d[2] = wmma::__float_to_tf32(v.z);
            d[3] = wmma::__float_to_tf32(v.w);
        }
        __syncthreads();

        #pragma unroll
        for (int ks = 0; ks < 8; ks++){
            wmma::fragment<wmma::matrix_a, 16,16,8, wmma::precision::tf32, wmma::row_major> a;
            wmma::load_matrix_sync(a, Xs + (warp*16)*XS_STRIDE + ks*8, XS_STRIDE);
            #pragma unroll
            for (int c = 0; c < 8; c++){
                wmma::fragment<wmma::matrix_b, 16,16,8, wmma::precision::tf32, wmma::row_major> b;
                wmma::load_matrix_sync(b, Ws + (ks*8)*WS_STRIDE + c*16, WS_STRIDE);
                wmma::mma_sync(acc[c], a, b, acc[c]);
            }
        }
        __syncthreads();
    }

    float* OutS = sm;                     // 128 x WS_STRIDE
    #pragma unroll
    for (int c = 0; c < 8; c++)
        wmma::store_matrix_sync(OutS + (warp*16)*WS_STRIDE + c*16, acc[c], WS_STRIDE, wmma::mem_row_major);
    __syncthreads();

    float gate = 1.f, og = 0.f;
    if (mode & 2){ gate = 1.f/(1.f + expf(-skipPtr[0])); og = 1.f - gate; }
    #pragma unroll
    for (int i = 0; i < 16; i++){
        int idx = tid + i*256;
        int r = idx >> 5, c4 = idx & 31;
        int gr = bRow + r;
        if (gr >= N) continue;
        const float* o = OutS + r*WS_STRIDE + c4*4;
        float4 bv = ((const float4*)B)[cb4 + c4];
        float4 res;
        res.x = o[0] + bv.x; res.y = o[1] + bv.y;
        res.z = o[2] + bv.z; res.w = o[3] + bv.w;
        if (mode & 2){
            float4 xo = ((const float4*)Xold)[(size_t)gr*32 + c4];
            res.x = gate*res.x + og*xo.x; res.y = gate*res.y + og*xo.y;
            res.z = gate*res.z + og*xo.z; res.w = gate*res.w + og*xo.w;
        }
        ((float4*)Y)[(size_t)gr*ldy4 + cb4 + c4] = res;
    }
}

// ---------------- combined weight prep ----------------
// paper buf [q k1 v1 k2 v2] (fold with a/m_rel e=1,2); author buf [q k0 v0] (e=0)
__global__ void prep_weights(const float* __restrict__ k_w, const float* __restrict__ k_b,
                             const float* __restrict__ v_w, const float* __restrict__ v_b,
                             const float* __restrict__ q_w, const float* __restrict__ q_b,
                             const float* __restrict__ a_rel, const float* __restrict__ m_rel)
{
    int fid = blockIdx.x;           // 0..15
    int l = fid >> 3, sid = fid & 7;
    bool paper = sid < 5;
    float* dstBase; int stride, col;
    if (paper){ dstBase = g_wp + l*WP_SZ; stride = 640; col = sid*128; }
    else      { dstBase = g_wa + l*WA_SZ; stride = 384; col = (sid-5)*128; }

    const float *W, *Bi, *R = nullptr;
    int t = paper ? 0 : 1;          // node type of the GEMM input
    switch (sid){
        case 0: W = q_w + (size_t)(l*2+0)*16384; Bi = q_b + (l*2+0)*128; break;
        case 1: W = k_w + (size_t)(l*2+0)*16384; Bi = k_b + (l*2+0)*128; R = a_rel + (size_t)(l*3+1)*4096; break;
        case 2: W = v_w + (size_t)(l*2+0)*16384; Bi = v_b + (l*2+0)*128; R = m_rel + (size_t)(l*3+1)*4096; break;
        case 3: W = k_w + (size_t)(l*2+0)*16384; Bi = k_b + (l*2+0)*128; R = a_rel + (size_t)(l*3+2)*4096; break;
        case 4: W = v_w + (size_t)(l*2+0)*16384; Bi = v_b + (l*2+0)*128; R = m_rel + (size_t)(l*3+2)*4096; break;
        case 5: W = q_w + (size_t)(l*2+1)*16384; Bi = q_b + (l*2+1)*128; break;
        case 6: W = k_w + (size_t)(l*2+1)*16384; Bi = k_b + (l*2+1)*128; R = a_rel + (size_t)(l*3+0)*4096; break;
        default:W = v_w + (size_t)(l*2+1)*16384; Bi = v_b + (l*2+1)*128; R = m_rel + (size_t)(l*3+0)*4096; break;
    }
    (void)t;

    int jc = threadIdx.x;
    int i0 = blockIdx.y * 32;
    if (R == nullptr){
        for (int i = i0; i < i0+32; i++) dstBase[i*stride + col + jc] = W[i*128 + jc];
        if (blockIdx.y == 0) dstBase[128*stride + col + jc] = Bi[jc];
        return;
    }
    __shared__ float Rs[4096];
    for (int i = threadIdx.x; i < 4096; i += 128) Rs[i] = R[i];
    __syncthreads();
    int h = jc >> 5, j = jc & 31;
    const float* Rh = Rs + h*1024 + j;
    for (int i = i0; i < i0+32; i++){
        float acc = 0.f;
        #pragma unroll
        for (int d = 0; d < 32; d++) acc += W[i*128 + h*32 + d] * Rh[d*32];
        dstBase[i*stride + col + jc] = acc;
    }
    if (blockIdx.y == 0){
        float accb = 0.f;
        #pragma unroll
        for (int d = 0; d < 32; d++) accb += Bi[h*32 + d] * Rh[d*32];
        dstBase[128*stride + col + jc] = accb;
    }
}

// ---------------- merged CSR build over (type,node) ----------------
__global__ void zero_int_kernel(int* __restrict__ p, int n){
    int i = blockIdx.x*blockDim.x + threadIdx.x;
    if (i < n) p[i] = 0;
}
__global__ void hist3_kernel(const int* __restrict__ d0, const int* __restrict__ d1,
                             const int* __restrict__ d2, int* __restrict__ deg){
    int i = blockIdx.x*blockDim.x + threadIdx.x;
    if (i >= 3*NEDGE) return;
    int t = i / NEDGE, e = i - t*NEDGE;
    int d = (t == 0) ? d0[e] : (t == 1) ? d1[e] : d2[e];
    atomicAdd(&deg[t*NP + d], 1);
}
__global__ void partial_kernel(const int* __restrict__ deg, int* __restrict__ part, int n){
    __shared__ int s[256];
    int tid = threadIdx.x;
    int base = blockIdx.x*1024 + tid*4;
    int sum = 0;
    #pragma unroll
    for (int j = 0; j < 4; j++) if (base + j < n) sum += deg[base + j];
    s[tid] = sum; __syncthreads();
    for (int d = 128; d > 0; d >>= 1){
        if (tid < d) s[tid] += s[tid + d];
        __syncthreads();
    }
    if (tid == 0) part[blockIdx.x] = s[0];
}
__global__ void scan_part_kernel(int* __restrict__ part, int nb){
    __shared__ int s[512];
    int tid = threadIdx.x;
    int v = (tid < nb) ? part[tid] : 0;
    s[tid] = v; __syncthreads();
    for (int d = 1; d < 512; d <<= 1){
        int t = (tid >= d) ? s[tid - d] : 0;
        __syncthreads();
        s[tid] += t;
        __syncthreads();
    }
    if (tid < nb) part[tid] = s[tid] - v;
}
__global__ void offsets_kernel(const int* __restrict__ deg, const int* __restrict__ part,
                               int* __restrict__ off, int* __restrict__ cur, int n, int E){
    __shared__ int s[256];
    int tid = threadIdx.x;
    int base = blockIdx.x*1024 + tid*4;
    int v[4];
    #pragma unroll
    for (int j = 0; j < 4; j++) v[j] = (base + j < n) ? deg[base + j] : 0;
    int tsum = v[0]+v[1]+v[2]+v[3];
    s[tid] = tsum; __syncthreads();
    for (int d = 1; d < 256; d <<= 1){
        int t = (tid >= d) ? s[tid - d] : 0;
        __syncthreads();
        s[tid] += t;
        __syncthreads();
    }
    int run = s[tid] - tsum + part[blockIdx.x];
    #pragma unroll
    for (int j = 0; j < 4; j++){
        if (base + j < n){ off[base + j] = run; cur[base + j] = run; }
        run += v[j];
    }
    if (blockIdx.x == 0 && tid == 0) off[n] = E;
}
__global__ void scatter3_kernel(const int* __restrict__ d0, const int* __restrict__ d1,
                                const int* __restrict__ d2, const int* __restrict__ s0,
                                const int* __restrict__ s1, const int* __restrict__ s2,
                                int* __restrict__ cur, int* __restrict__ srcs){
    int i = blockIdx.x*blockDim.x + threadIdx.x;
    if (i >= 3*NEDGE) return;
    int t = i / NEDGE, e = i - t*NEDGE;
    int d  = (t == 0) ? d0[e] : (t == 1) ? d1[e] : d2[e];
    int sv = (t == 0) ? s0[e] : (t == 1) ? s1[e] : s2[e];
    int pos = atomicAdd(&cur[t*NP + d], 1);
    srcs[pos] = sv;
}

// ---------------- single-pass fused attention aggregation ----------------
__device__ __forceinline__ float4 agg_one(int e0, int e1, const int* __restrict__ srcs,
                                          const float4* __restrict__ buf, int stride4,
                                          int kOff4, int vOff4, float ph, float4 q4, int lane)
{
    float den = 0.f;
    float4 acc = make_float4(0.f,0.f,0.f,0.f);
    for (int base = e0; base < e1; base += 32){
        int m = min(32, e1 - base);
        int myS = (base + lane < e1) ? srcs[base + lane] : 0;
        for (int j = 0; j < m; j++){
            int s = __shfl_sync(0xffffffffu, myS, j);
            const float4* row = buf + (size_t)s*stride4;
            float4 k4 = row[kOff4 + lane];
            float4 v4 = row[vOff4 + lane];
            float p = q4.x*k4.x + q4.y*k4.y + q4.z*k4.z + q4.w*k4.w;
            p += __shfl_xor_sync(0xffffffffu, p, 1);
            p += __shfl_xor_sync(0xffffffffu, p, 2);
            p += __shfl_xor_sync(0xffffffffu, p, 4);
            float ex = __expf(p * ph);
            den += ex;
            acc.x += ex*v4.x; acc.y += ex*v4.y;
            acc.z += ex*v4.z; acc.w += ex*v4.w;
        }
    }
    float inv = 1.f/(den + 1e-16f);
    acc.x *= inv; acc.y *= inv; acc.z *= inv; acc.w *= inv;
    return acc;
}

__global__ void aggregate_fused(const int* __restrict__ off, const int* __restrict__ srcs,
                                int offBaseA, const float4* __restrict__ bufA, int strideA4,
                                int kOffA4, int vOffA4, const float* __restrict__ prelA,
                                int useB,
                                int offBaseB, const float4* __restrict__ bufB, int strideB4,
                                int kOffB4, int vOffB4, const float* __restrict__ prelB,
                                const float4* __restrict__ Q, int strideQ4,
                                float4* __restrict__ OUT, int Nd)
{
    int d = blockIdx.x*8 + (threadIdx.x >> 5);
    if (d >= Nd) return;
    int lane = threadIdx.x & 31;
    int h = lane >> 3;
    float4 q4 = Q[(size_t)d*strideQ4 + lane];

    float phA = prelA[h] * 0.17677669529663687f;
    float4 res = agg_one(off[offBaseA + d], off[offBaseA + d + 1], srcs,
                         bufA, strideA4, kOffA4, vOffA4, phA, q4, lane);
    if (useB){
        float phB = prelB[h] * 0.17677669529663687f;
        float4 r2 = agg_one(off[offBaseB + d], off[offBaseB + d + 1], srcs,
                            bufB, strideB4, kOffB4, vOffB4, phB, q4, lane);
        res.x += r2.x; res.y += r2.y; res.z += r2.z; res.w += r2.w;
    }
    OUT[(size_t)d*32 + lane] = res;
}

// ---------------- misc ----------------
__global__ void gather_embed_kernel(const float* __restrict__ tab, const int* __restrict__ idx,
                                    float* __restrict__ out, int n){
    int i = blockIdx.x*blockDim.x + threadIdx.x;
    if (i >= n*32) return;
    int node = i >> 5, c = i & 31;
    int src = idx[node];
    ((float4*)out)[(size_t)node*32 + c] = ((const float4*)tab)[(size_t)src*32 + c];
}
__global__ void copy_out_kernel(const float* __restrict__ xp, const float* __restrict__ xa,
                                float4* __restrict__ out){
    int i = blockIdx.x*blockDim.x + threadIdx.x;
    const int n1 = 50000*32, n2 = 25000*32;
    if (i < n1) out[i] = ((const float4*)xp)[i];
    else if (i < n1 + n2) out[i] = ((const float4*)xa)[i - n1];
}

// ---------------- launch ----------------
extern "C" void kernel_launch(void* const* d_in, const int* in_sizes, int n_in,
                              void* d_out, int out_size)
{
    const float* x_paper     = (const float*)d_in[0];
    const int*   author_idx  = (const int*)  d_in[1];
    const float* embed_table = (const float*)d_in[2];
    const float* lin_w       = (const float*)d_in[3];
    const float* lin_b       = (const float*)d_in[4];
    const float* k_w         = (const float*)d_in[5];
    const float* k_b         = (const float*)d_in[6];
    const float* q_w         = (const float*)d_in[7];
    const float* q_b         = (const float*)d_in[8];
    const float* v_w         = (const float*)d_in[9];
    const float* v_b         = (const float*)d_in[10];
    const float* a_rel       = (const float*)d_in[11];
    const float* m_rel       = (const float*)d_in[12];
    const float* p_rel       = (const float*)d_in[13];
    const float* skip        = (const float*)d_in[14];
    const float* a_w         = (const float*)d_in[15];
    const float* a_b         = (const float*)d_in[16];
    const int*   w_src       = (const int*)  d_in[17];
    const int*   w_dst       = (const int*)  d_in[18];
    const int*   r_src       = (const int*)  d_in[19];
    const int*   r_dst       = (const int*)  d_in[20];
    const int*   c_src       = (const int*)  d_in[21];
    const int*   c_dst       = (const int*)  d_in[22];
    float* out = (float*)d_out;

    float *xp,*xa,*actp,*acta,*aggp,*agga,*wp,*wa;
    int *deg,*off,*cur,*srcs,*part;
    cudaGetSymbolAddress((void**)&xp,   g_xp);
    cudaGetSymbolAddress((void**)&xa,   g_xa);
    cudaGetSymbolAddress((void**)&actp, g_actp);
    cudaGetSymbolAddress((void**)&acta, g_acta);
    cudaGetSymbolAddress((void**)&aggp, g_aggp);
    cudaGetSymbolAddress((void**)&agga, g_agga);
    cudaGetSymbolAddress((void**)&wp,   g_wp);
    cudaGetSymbolAddress((void**)&wa,   g_wa);
    cudaGetSymbolAddress((void**)&deg,  g_deg);
    cudaGetSymbolAddress((void**)&off,  g_off);
    cudaGetSymbolAddress((void**)&cur,  g_cur);
    cudaGetSymbolAddress((void**)&srcs, g_srcs);
    cudaGetSymbolAddress((void**)&part, g_part);

    cudaFuncSetAttribute(gemm128_tc, cudaFuncAttributeMaxDynamicSharedMemorySize, SMEM_FLOATS*4);

    // merged CSR build
    {
        int n = 3*NP;
        int nb = (n + 1023)/1024;   // 293
        zero_int_kernel<<<(n+255)/256,256>>>(deg, n);
        hist3_kernel<<<(3*NEDGE+255)/256,256>>>(w_dst, r_dst, c_dst, deg);
        partial_kernel<<<nb,256>>>(deg, part, n);
        scan_part_kernel<<<1,512>>>(part, nb);
        offsets_kernel<<<nb,256>>>(deg, part, off, cur, n, 3*NEDGE);
        scatter3_kernel<<<(3*NEDGE+255)/256,256>>>(w_dst, r_dst, c_dst, w_src, r_src, c_src, cur, srcs);
    }

    prep_weights<<<dim3(16,4),128>>>(k_w, k_b, v_w, v_b, q_w, q_b, a_rel, m_rel);

    const int SMB = SMEM_FLOATS*4;
    const int GP = (NP+127)/128, GA = (NA+127)/128;

    gemm128_tc<<<dim3(GP,1),256,SMB>>>(x_paper, lin_w, 128, lin_b, xp, 128, nullptr, nullptr, NP, 0, 1.f);
    gather_embed_kernel<<<(NA*32+255)/256,256>>>(embed_table, author_idx, xa, NA);

    for (int l = 0; l < 2; l++){
        // fused QKV projections
        gemm128_tc<<<dim3(GP,5),256,SMB>>>(xp, wp + l*WP_SZ, 640, wp + l*WP_SZ + 128*640,
                                           actp, 640, nullptr, nullptr, NP, 0, 1.f);
        gemm128_tc<<<dim3(GA,3),256,SMB>>>(xa, wa + l*WA_SZ, 384, wa + l*WA_SZ + 128*384,
                                           acta, 384, nullptr, nullptr, NA, 0, 1.f);

        // paper dst: e0 (author src: k0/v0 in acta) + e2 (paper src: k2/v2 in actp)
        aggregate_fused<<<(NP+7)/8,256>>>(off, srcs,
            0*NP,  (const float4*)acta, 96, 32, 64, p_rel + (l*3+0)*4,
            1,
            2*NP,  (const float4*)actp, 160, 96, 128, p_rel + (l*3+2)*4,
            (const float4*)actp, 160, (float4*)aggp, NP);
        // author dst: e1 (paper src: k1/v1 in actp)
        aggregate_fused<<<(NA+7)/8,256>>>(off, srcs,
            1*NP,  (const float4*)actp, 160, 32, 64, p_rel + (l*3+1)*4,
            0,
            0, nullptr, 0, 0, 0, nullptr,
            (const float4*)acta, 96, (float4*)agga, NA);

        // update: y = sigmoid(skip)*(gelu(mean)@a_w + a_b) + (1-sigmoid(skip))*x
        gemm128_tc<<<dim3(GP,1),256,SMB>>>(aggp, a_w + (size_t)(l*2+0)*16384, 128, a_b + (l*2+0)*128,
                                           xp, 128, xp, skip + l*2+0, NP, 3, 0.5f);
        gemm128_tc<<<dim3(GA,1),256,SMB>>>(agga, a_w + (size_t)(l*2+1)*16384, 128, a_b + (l*2+1)*128,
                                           xa, 128, xa, skip + l*2+1, NA, 3, 1.0f);
    }

    copy_out_kernel<<<(2400000+255)/256,256>>>(xp, xa, (float4*)out);
}

// round 5
// speedup vs baseline: 1.6079x; 1.1064x over previous
#include <cuda_runtime.h>
#include <math.h>
#include <mma.h>

using namespace nvcuda;

#define NP 100000
#define NA 50000
#define NEDGE 250000

#define XS_STRIDE 68
#define WS_STRIDE 132
#define SMEM_FLOATS (128*XS_STRIDE + 64*WS_STRIDE)

#define WP_SZ (128*640 + 640)
#define WA_SZ (128*384 + 384)

// ---------------- scratch ----------------
__device__ float g_xp[NP*128];
__device__ float g_xa[NA*128];
__device__ float g_actp[(size_t)NP*640];   // [q k1 v1 k2 v2]
__device__ float g_acta[(size_t)NA*384];   // [q k0 v0]
__device__ float g_aggp[NP*128];
__device__ float g_agga[NA*128];
__device__ float g_wp[2*WP_SZ];
__device__ float g_wa[2*WA_SZ];
__device__ int   g_deg[3*NP];
__device__ int   g_off[3*NP+1];
__device__ int   g_cur[3*NP];
__device__ int   g_srcs[3*NEDGE];
__device__ int   g_part[512];

__device__ __forceinline__ float gelu_f(float x){
    return 0.5f*x*(1.0f + erff(x*0.70710678118654752f));
}

// ---------------- tf32 tensor-core GEMM: [N,128] x [128,Nw] ----------------
// warp subtile 32x64 (4 row groups x 2 col groups) => 3 fragment-loads per mma
// mode bit0: gelu(inScale*x) on input ; bit1: blend y = g*(acc+b)+(1-g)*Xold
// mode bit2: also write rows < out2N to out2 (ld 128)
__global__ void gemm128_tc(const float* __restrict__ X, const float* __restrict__ W, int ldw,
                           const float* __restrict__ B, float* __restrict__ Y, int ldy,
                           const float* __restrict__ Xold, const float* __restrict__ skipPtr,
                           float* __restrict__ out2, int out2N,
                           int N, int mode, float inScale)
{
    extern __shared__ float sm[];
    float* Xs = sm;                       // 128 x XS_STRIDE (64 cols used)
    float* Ws = sm + 128*XS_STRIDE;       // 64  x WS_STRIDE (128 cols used)
    const int tid  = threadIdx.x;
    const int warp = tid >> 5;
    const int wr   = warp >> 1;           // 0..3  (row group, 32 rows)
    const int wc   = warp & 1;            // 0..1  (col group, 64 cols)
    const int bRow = blockIdx.x * 128;
    const int colBase = blockIdx.y * 128;
    const int ldw4 = ldw >> 2, ldy4 = ldy >> 2, cb4 = colBase >> 2;

    wmma::fragment<wmma::accumulator, 16,16,8, float> acc[2][4];
    #pragma unroll
    for (int i = 0; i < 2; i++)
        #pragma unroll
        for (int c = 0; c < 4; c++) wmma::fill_fragment(acc[i][c], 0.f);

    #pragma unroll
    for (int kk = 0; kk < 128; kk += 64){
        #pragma unroll
        for (int i = 0; i < 8; i++){
            int idx = tid + i*256;
            int r = idx >> 4, c4 = idx & 15;
            int gr = bRow + r;
            float4 v = make_float4(0.f,0.f,0.f,0.f);
            if (gr < N) v = ((const float4*)X)[(size_t)gr*32 + (kk>>2) + c4];
            if (mode & 1){
                v.x = gelu_f(v.x*inScale); v.y = gelu_f(v.y*inScale);
                v.z = gelu_f(v.z*inScale); v.w = gelu_f(v.w*inScale);
            }
            float* d = Xs + r*XS_STRIDE + c4*4;
            d[0] = wmma::__float_to_tf32(v.x);
            d[1] = wmma::__float_to_tf32(v.y);
            d[2] = wmma::__float_to_tf32(v.z);
            d[3] = wmma::__float_to_tf32(v.w);
        }
        #pragma unroll
        for (int i = 0; i < 8; i++){
            int idx = tid + i*256;
            int r = idx >> 5, c4 = idx & 31;
            float4 v = ((const float4*)W)[(size_t)(kk + r)*ldw4 + cb4 + c4];
            float* d = Ws + r*WS_STRIDE + c4*4;
            d[0] = wmma::__float_to_tf32(v.x);
            d[1] = wmma::__float_to_tf32(v.y);
            d[2] = wmma::__float_to_tf32(v.z);
            d[3] = wmma::__float_to_tf32(v.w);
        }
        __syncthreads();

        #pragma unroll
        for (int ks = 0; ks < 8; ks++){
            wmma::fragment<wmma::matrix_a, 16,16,8, wmma::precision::tf32, wmma::row_major> a0, a1;
            wmma::load_matrix_sync(a0, Xs + (wr*32   )*XS_STRIDE + ks*8, XS_STRIDE);
            wmma::load_matrix_sync(a1, Xs + (wr*32+16)*XS_STRIDE + ks*8, XS_STRIDE);
            #pragma unroll
            for (int c = 0; c < 4; c++){
                wmma::fragment<wmma::matrix_b, 16,16,8, wmma::precision::tf32, wmma::row_major> b;
                wmma::load_matrix_sync(b, Ws + (ks*8)*WS_STRIDE + wc*64 + c*16, WS_STRIDE);
                wmma::mma_sync(acc[0][c], a0, b, acc[0][c]);
                wmma::mma_sync(acc[1][c], a1, b, acc[1][c]);
            }
        }
        __syncthreads();
    }

    float* OutS = sm;                     // 128 x WS_STRIDE
    #pragma unroll
    for (int i = 0; i < 2; i++)
        #pragma unroll
        for (int c = 0; c < 4; c++)
            wmma::store_matrix_sync(OutS + (wr*32 + i*16)*WS_STRIDE + wc*64 + c*16,
                                    acc[i][c], WS_STRIDE, wmma::mem_row_major);
    __syncthreads();

    float gate = 1.f, og = 0.f;
    if (mode & 2){ gate = 1.f/(1.f + expf(-skipPtr[0])); og = 1.f - gate; }
    #pragma unroll
    for (int i = 0; i < 16; i++){
        int idx = tid + i*256;
        int r = idx >> 5, c4 = idx & 31;
        int gr = bRow + r;
        if (gr >= N) continue;
        const float* o = OutS + r*WS_STRIDE + c4*4;
        float4 bv = ((const float4*)B)[cb4 + c4];
        float4 res;
        res.x = o[0] + bv.x; res.y = o[1] + bv.y;
        res.z = o[2] + bv.z; res.w = o[3] + bv.w;
        if (mode & 2){
            float4 xo = ((const float4*)Xold)[(size_t)gr*32 + c4];
            res.x = gate*res.x + og*xo.x; res.y = gate*res.y + og*xo.y;
            res.z = gate*res.z + og*xo.z; res.w = gate*res.w + og*xo.w;
        }
        ((float4*)Y)[(size_t)gr*ldy4 + cb4 + c4] = res;
        if ((mode & 4) && gr < out2N)
            ((float4*)out2)[(size_t)gr*32 + c4] = res;
    }
}

// ---------------- combined weight prep ----------------
__global__ void prep_weights(const float* __restrict__ k_w, const float* __restrict__ k_b,
                             const float* __restrict__ v_w, const float* __restrict__ v_b,
                             const float* __restrict__ q_w, const float* __restrict__ q_b,
                             const float* __restrict__ a_rel, const float* __restrict__ m_rel)
{
    int fid = blockIdx.x;           // 0..15
    int l = fid >> 3, sid = fid & 7;
    bool paper = sid < 5;
    float* dstBase; int stride, col;
    if (paper){ dstBase = g_wp + l*WP_SZ; stride = 640; col = sid*128; }
    else      { dstBase = g_wa + l*WA_SZ; stride = 384; col = (sid-5)*128; }

    const float *W, *Bi, *R = nullptr;
    switch (sid){
        case 0: W = q_w + (size_t)(l*2+0)*16384; Bi = q_b + (l*2+0)*128; break;
        case 1: W = k_w + (size_t)(l*2+0)*16384; Bi = k_b + (l*2+0)*128; R = a_rel + (size_t)(l*3+1)*4096; break;
        case 2: W = v_w + (size_t)(l*2+0)*16384; Bi = v_b + (l*2+0)*128; R = m_rel + (size_t)(l*3+1)*4096; break;
        case 3: W = k_w + (size_t)(l*2+0)*16384; Bi = k_b + (l*2+0)*128; R = a_rel + (size_t)(l*3+2)*4096; break;
        case 4: W = v_w + (size_t)(l*2+0)*16384; Bi = v_b + (l*2+0)*128; R = m_rel + (size_t)(l*3+2)*4096; break;
        case 5: W = q_w + (size_t)(l*2+1)*16384; Bi = q_b + (l*2+1)*128; break;
        case 6: W = k_w + (size_t)(l*2+1)*16384; Bi = k_b + (l*2+1)*128; R = a_rel + (size_t)(l*3+0)*4096; break;
        default:W = v_w + (size_t)(l*2+1)*16384; Bi = v_b + (l*2+1)*128; R = m_rel + (size_t)(l*3+0)*4096; break;
    }

    int jc = threadIdx.x;
    int i0 = blockIdx.y * 32;
    if (R == nullptr){
        for (int i = i0; i < i0+32; i++) dstBase[i*stride + col + jc] = W[i*128 + jc];
        if (blockIdx.y == 0) dstBase[128*stride + col + jc] = Bi[jc];
        return;
    }
    __shared__ float Rs[4096];
    for (int i = threadIdx.x; i < 4096; i += 128) Rs[i] = R[i];
    __syncthreads();
    int h = jc >> 5, j = jc & 31;
    const float* Rh = Rs + h*1024 + j;
    for (int i = i0; i < i0+32; i++){
        float acc = 0.f;
        #pragma unroll
        for (int d = 0; d < 32; d++) acc += W[i*128 + h*32 + d] * Rh[d*32];
        dstBase[i*stride + col + jc] = acc;
    }
    if (blockIdx.y == 0){
        float accb = 0.f;
        #pragma unroll
        for (int d = 0; d < 32; d++) accb += Bi[h*32 + d] * Rh[d*32];
        dstBase[128*stride + col + jc] = accb;
    }
}

// ---------------- merged CSR build over (type,node) ----------------
__global__ void zero_int_kernel(int* __restrict__ p, int n){
    int i = blockIdx.x*blockDim.x + threadIdx.x;
    if (i < n) p[i] = 0;
}
__global__ void hist3_kernel(const int* __restrict__ d0, const int* __restrict__ d1,
                             const int* __restrict__ d2, int* __restrict__ deg){
    int i = blockIdx.x*blockDim.x + threadIdx.x;
    if (i >= 3*NEDGE) return;
    int t = i / NEDGE, e = i - t*NEDGE;
    int d = (t == 0) ? d0[e] : (t == 1) ? d1[e] : d2[e];
    atomicAdd(&deg[t*NP + d], 1);
}
__global__ void partial_kernel(const int* __restrict__ deg, int* __restrict__ part, int n){
    __shared__ int s[256];
    int tid = threadIdx.x;
    int base = blockIdx.x*1024 + tid*4;
    int sum = 0;
    #pragma unroll
    for (int j = 0; j < 4; j++) if (base + j < n) sum += deg[base + j];
    s[tid] = sum; __syncthreads();
    for (int d = 128; d > 0; d >>= 1){
        if (tid < d) s[tid] += s[tid + d];
        __syncthreads();
    }
    if (tid == 0) part[blockIdx.x] = s[0];
}
__global__ void scan_part_kernel(int* __restrict__ part, int nb){
    __shared__ int s[512];
    int tid = threadIdx.x;
    int v = (tid < nb) ? part[tid] : 0;
    s[tid] = v; __syncthreads();
    for (int d = 1; d < 512; d <<= 1){
        int t = (tid >= d) ? s[tid - d] : 0;
        __syncthreads();
        s[tid] += t;
        __syncthreads();
    }
    if (tid < nb) part[tid] = s[tid] - v;
}
__global__ void offsets_kernel(const int* __restrict__ deg, const int* __restrict__ part,
                               int* __restrict__ off, int* __restrict__ cur, int n, int E){
    __shared__ int s[256];
    int tid = threadIdx.x;
    int base = blockIdx.x*1024 + tid*4;
    int v[4];
    #pragma unroll
    for (int j = 0; j < 4; j++) v[j] = (base + j < n) ? deg[base + j] : 0;
    int tsum = v[0]+v[1]+v[2]+v[3];
    s[tid] = tsum; __syncthreads();
    for (int d = 1; d < 256; d <<= 1){
        int t = (tid >= d) ? s[tid - d] : 0;
        __syncthreads();
        s[tid] += t;
        __syncthreads();
    }
    int run = s[tid] - tsum + part[blockIdx.x];
    #pragma unroll
    for (int j = 0; j < 4; j++){
        if (base + j < n){ off[base + j] = run; cur[base + j] = run; }
        run += v[j];
    }
    if (blockIdx.x == 0 && tid == 0) off[n] = E;
}
__global__ void scatter3_kernel(const int* __restrict__ d0, const int* __restrict__ d1,
                                const int* __restrict__ d2, const int* __restrict__ s0,
                                const int* __restrict__ s1, const int* __restrict__ s2,
                                int* __restrict__ cur, int* __restrict__ srcs){
    int i = blockIdx.x*blockDim.x + threadIdx.x;
    if (i >= 3*NEDGE) return;
    int t = i / NEDGE, e = i - t*NEDGE;
    int d  = (t == 0) ? d0[e] : (t == 1) ? d1[e] : d2[e];
    int sv = (t == 0) ? s0[e] : (t == 1) ? s1[e] : s2[e];
    int pos = atomicAdd(&cur[t*NP + d], 1);
    srcs[pos] = sv;
}

// ---------------- single-pass fused attention aggregation (all dsts) ----------------
__device__ __forceinline__ float4 agg_one(int e0, int e1, const int* __restrict__ srcs,
                                          const float4* __restrict__ buf, int stride4,
                                          int kOff4, int vOff4, float ph, float4 q4, int lane)
{
    float den = 0.f;
    float4 acc = make_float4(0.f,0.f,0.f,0.f);
    for (int base = e0; base < e1; base += 32){
        int m = min(32, e1 - base);
        int myS = (base + lane < e1) ? srcs[base + lane] : 0;
        int j = 0;
        for (; j + 2 <= m; j += 2){
            int sA = __shfl_sync(0xffffffffu, myS, j);
            int sB = __shfl_sync(0xffffffffu, myS, j+1);
            const float4* rA = buf + (size_t)sA*stride4;
            const float4* rB = buf + (size_t)sB*stride4;
            float4 kA = rA[kOff4 + lane];
            float4 vA = rA[vOff4 + lane];
            float4 kB = rB[kOff4 + lane];
            float4 vB = rB[vOff4 + lane];
            float pA = q4.x*kA.x + q4.y*kA.y + q4.z*kA.z + q4.w*kA.w;
            float pB = q4.x*kB.x + q4.y*kB.y + q4.z*kB.z + q4.w*kB.w;
            pA += __shfl_xor_sync(0xffffffffu, pA, 1);
            pB += __shfl_xor_sync(0xffffffffu, pB, 1);
            pA += __shfl_xor_sync(0xffffffffu, pA, 2);
            pB += __shfl_xor_sync(0xffffffffu, pB, 2);
            pA += __shfl_xor_sync(0xffffffffu, pA, 4);
            pB += __shfl_xor_sync(0xffffffffu, pB, 4);
            float eA = __expf(pA * ph);
            float eB = __expf(pB * ph);
            den += eA + eB;
            acc.x += eA*vA.x + eB*vB.x;
            acc.y += eA*vA.y + eB*vB.y;
            acc.z += eA*vA.z + eB*vB.z;
            acc.w += eA*vA.w + eB*vB.w;
        }
        if (j < m){
            int s = __shfl_sync(0xffffffffu, myS, j);
            const float4* row = buf + (size_t)s*stride4;
            float4 k4 = row[kOff4 + lane];
            float4 v4 = row[vOff4 + lane];
            float p = q4.x*k4.x + q4.y*k4.y + q4.z*k4.z + q4.w*k4.w;
            p += __shfl_xor_sync(0xffffffffu, p, 1);
            p += __shfl_xor_sync(0xffffffffu, p, 2);
            p += __shfl_xor_sync(0xffffffffu, p, 4);
            float ex = __expf(p * ph);
            den += ex;
            acc.x += ex*v4.x; acc.y += ex*v4.y;
            acc.z += ex*v4.z; acc.w += ex*v4.w;
        }
    }
    float inv = 1.f/(den + 1e-16f);
    acc.x *= inv; acc.y *= inv; acc.z *= inv; acc.w *= inv;
    return acc;
}

__global__ void aggregate_all(const int* __restrict__ off, const int* __restrict__ srcs,
                              const float4* __restrict__ actp, const float4* __restrict__ acta,
                              const float* __restrict__ prel,   // 12 floats for this layer
                              float4* __restrict__ aggp, float4* __restrict__ agga)
{
    int d = blockIdx.x*8 + (threadIdx.x >> 5);
    int lane = threadIdx.x & 31;
    int h = lane >> 3;
    if (d < NP){
        float4 q4 = actp[(size_t)d*160 + lane];
        float ph0 = prel[0*4 + h] * 0.17677669529663687f;
        float ph2 = prel[2*4 + h] * 0.17677669529663687f;
        float4 res = agg_one(off[d], off[d+1], srcs, acta, 96, 32, 64, ph0, q4, lane);
        float4 r2  = agg_one(off[2*NP+d], off[2*NP+d+1], srcs, actp, 160, 96, 128, ph2, q4, lane);
        res.x += r2.x; res.y += r2.y; res.z += r2.z; res.w += r2.w;
        aggp[(size_t)d*32 + lane] = res;
    } else if (d < NP + NA){
        int da = d - NP;
        float4 q4 = acta[(size_t)da*96 + lane];
        float ph1 = prel[1*4 + h] * 0.17677669529663687f;
        float4 res = agg_one(off[NP+da], off[NP+da+1], srcs, actp, 160, 32, 64, ph1, q4, lane);
        agga[(size_t)da*32 + lane] = res;
    }
}

// ---------------- misc ----------------
__global__ void gather_embed_kernel(const float* __restrict__ tab, const int* __restrict__ idx,
                                    float* __restrict__ out, int n){
    int i = blockIdx.x*blockDim.x + threadIdx.x;
    if (i >= n*32) return;
    int node = i >> 5, c = i & 31;
    int src = idx[node];
    ((float4*)out)[(size_t)node*32 + c] = ((const float4*)tab)[(size_t)src*32 + c];
}

// ---------------- launch ----------------
extern "C" void kernel_launch(void* const* d_in, const int* in_sizes, int n_in,
                              void* d_out, int out_size)
{
    const float* x_paper     = (const float*)d_in[0];
    const int*   author_idx  = (const int*)  d_in[1];
    const float* embed_table = (const float*)d_in[2];
    const float* lin_w       = (const float*)d_in[3];
    const float* lin_b       = (const float*)d_in[4];
    const float* k_w         = (const float*)d_in[5];
    const float* k_b         = (const float*)d_in[6];
    const float* q_w         = (const float*)d_in[7];
    const float* q_b         = (const float*)d_in[8];
    const float* v_w         = (const float*)d_in[9];
    const float* v_b         = (const float*)d_in[10];
    const float* a_rel       = (const float*)d_in[11];
    const float* m_rel       = (const float*)d_in[12];
    const float* p_rel       = (const float*)d_in[13];
    const float* skip        = (const float*)d_in[14];
    const float* a_w         = (const float*)d_in[15];
    const float* a_b         = (const float*)d_in[16];
    const int*   w_src       = (const int*)  d_in[17];
    const int*   w_dst       = (const int*)  d_in[18];
    const int*   r_src       = (const int*)  d_in[19];
    const int*   r_dst       = (const int*)  d_in[20];
    const int*   c_src       = (const int*)  d_in[21];
    const int*   c_dst       = (const int*)  d_in[22];
    float* out = (float*)d_out;

    float *xp,*xa,*actp,*acta,*aggp,*agga,*wp,*wa;
    int *deg,*off,*cur,*srcs,*part;
    cudaGetSymbolAddress((void**)&xp,   g_xp);
    cudaGetSymbolAddress((void**)&xa,   g_xa);
    cudaGetSymbolAddress((void**)&actp, g_actp);
    cudaGetSymbolAddress((void**)&acta, g_acta);
    cudaGetSymbolAddress((void**)&aggp, g_aggp);
    cudaGetSymbolAddress((void**)&agga, g_agga);
    cudaGetSymbolAddress((void**)&wp,   g_wp);
    cudaGetSymbolAddress((void**)&wa,   g_wa);
    cudaGetSymbolAddress((void**)&deg,  g_deg);
    cudaGetSymbolAddress((void**)&off,  g_off);
    cudaGetSymbolAddress((void**)&cur,  g_cur);
    cudaGetSymbolAddress((void**)&srcs, g_srcs);
    cudaGetSymbolAddress((void**)&part, g_part);

    cudaFuncSetAttribute(gemm128_tc, cudaFuncAttributeMaxDynamicSharedMemorySize, SMEM_FLOATS*4);

    const int SMB = SMEM_FLOATS*4;
    const int GP = (NP+127)/128, GA = (NA+127)/128;

    // 1: weight prep ; 2: author embed gather ; 3: paper input projection
    prep_weights<<<dim3(16,4),128>>>(k_w, k_b, v_w, v_b, q_w, q_b, a_rel, m_rel);
    gather_embed_kernel<<<(NA*32+255)/256,256>>>(embed_table, author_idx, xa, NA);
    gemm128_tc<<<dim3(GP,1),256,SMB>>>(x_paper, lin_w, 128, lin_b, xp, 128, nullptr, nullptr,
                                       nullptr, 0, NP, 0, 1.f);

    for (int l = 0; l < 2; l++){
        // 4 (l=0): fused QKV projections  (ncu profiles the 4th launch)
        gemm128_tc<<<dim3(GP,5),256,SMB>>>(xp, wp + l*WP_SZ, 640, wp + l*WP_SZ + 128*640,
                                           actp, 640, nullptr, nullptr, nullptr, 0, NP, 0, 1.f);
        gemm128_tc<<<dim3(GA,3),256,SMB>>>(xa, wa + l*WA_SZ, 384, wa + l*WA_SZ + 128*384,
                                           acta, 384, nullptr, nullptr, nullptr, 0, NA, 0, 1.f);

        if (l == 0){
            // CSR build (needed before first aggregate; overlaps QKV in issue order)
            int n = 3*NP;
            int nb = (n + 1023)/1024;
            zero_int_kernel<<<(n+255)/256,256>>>(deg, n);
            hist3_kernel<<<(3*NEDGE+255)/256,256>>>(w_dst, r_dst, c_dst, deg);
            partial_kernel<<<nb,256>>>(deg, part, n);
            scan_part_kernel<<<1,512>>>(part, nb);
            offsets_kernel<<<nb,256>>>(deg, part, off, cur, n, 3*NEDGE);
            scatter3_kernel<<<(3*NEDGE+255)/256,256>>>(w_dst, r_dst, c_dst, w_src, r_src, c_src, cur, srcs);
        }

        aggregate_all<<<(NP+NA+7)/8,256>>>(off, srcs, (const float4*)actp, (const float4*)acta,
                                           p_rel + l*12, (float4*)aggp, (float4*)agga);

        // update: y = sigmoid(skip)*(gelu(mean)@a_w + a_b) + (1-sigmoid(skip))*x  (+ final out write)
        int modeP = (l == 1) ? 7 : 3, modeA = (l == 1) ? 7 : 3;
        gemm128_tc<<<dim3(GP,1),256,SMB>>>(aggp, a_w + (size_t)(l*2+0)*16384, 128, a_b + (l*2+0)*128,
                                           xp, 128, xp, skip + l*2+0,
                                           out, (l==1)?50000:0, NP, modeP, 0.5f);
        gemm128_tc<<<dim3(GA,1),256,SMB>>>(agga, a_w + (size_t)(l*2+1)*16384, 128, a_b + (l*2+1)*128,
                                           xa, 128, xa, skip + l*2+1,
                                           out + (size_t)50000*128, (l==1)?25000:0, NA, modeA, 1.0f);
    }
}

// round 6
// speedup vs baseline: 2.1026x; 1.3076x over previous
#include <cuda_runtime.h>
#include <math.h>
#include <mma.h>

using namespace nvcuda;

#define NP 100000
#define NA 50000
#define NEDGE 250000

#define XS_STRIDE 68
#define WS_STRIDE 132
#define SMEM_FLOATS (128*XS_STRIDE + 64*WS_STRIDE)

#define WP_SZ (128*640 + 640)
#define WA_SZ (128*384 + 384)

// ---------------- scratch ----------------
__device__ float g_xp[NP*128];
__device__ float g_xa[NA*128];
__device__ float g_actp[(size_t)NP*640];   // [q k1 v1 k2 v2]
__device__ float g_acta[(size_t)NA*384];   // [q k0 v0]
__device__ float g_aggp[NP*128];
__device__ float g_agga[NA*128];
__device__ float g_wp[2*WP_SZ];
__device__ float g_wa[2*WA_SZ];
__device__ int   g_deg[3*NP];
__device__ int   g_off[3*NP+1];
__device__ int   g_cur[3*NP];
__device__ int   g_srcs[3*NEDGE];
__device__ int   g_part[512];

__device__ __forceinline__ float gelu_f(float x){
    return 0.5f*x*(1.0f + erff(x*0.70710678118654752f));
}

// ---------------- tf32 tensor-core GEMM: [N,128] x [128,Nw] ----------------
// warp subtile 32x64 (4 row groups x 2 col groups) => 3 fragment-loads per mma
// mode bit0: gelu(inScale*x) on input ; bit1: blend y = g*(acc+b)+(1-g)*Xold
// mode bit2: also write rows < out2N to out2 (ld 128)
__global__ void __launch_bounds__(256, 2)
gemm128_tc(const float* __restrict__ X, const float* __restrict__ W, int ldw,
           const float* __restrict__ B, float* __restrict__ Y, int ldy,
           const float* __restrict__ Xold, const float* __restrict__ skipPtr,
           float* __restrict__ out2, int out2N,
           int N, int mode, float inScale)
{
    extern __shared__ float sm[];
    float* Xs = sm;                       // 128 x XS_STRIDE (64 cols used)
    float* Ws = sm + 128*XS_STRIDE;       // 64  x WS_STRIDE (128 cols used)
    const int tid  = threadIdx.x;
    const int warp = tid >> 5;
    const int wr   = warp >> 1;           // 0..3  (row group, 32 rows)
    const int wc   = warp & 1;            // 0..1  (col group, 64 cols)
    const int bRow = blockIdx.x * 128;
    const int colBase = blockIdx.y * 128;
    const int ldw4 = ldw >> 2, ldy4 = ldy >> 2, cb4 = colBase >> 2;

    wmma::fragment<wmma::accumulator, 16,16,8, float> acc[2][4];
    #pragma unroll
    for (int i = 0; i < 2; i++)
        #pragma unroll
        for (int c = 0; c < 4; c++) wmma::fill_fragment(acc[i][c], 0.f);

    #pragma unroll 1
    for (int kk = 0; kk < 128; kk += 64){
        #pragma unroll
        for (int i = 0; i < 8; i++){
            int idx = tid + i*256;
            int r = idx >> 4, c4 = idx & 15;
            int gr = bRow + r;
            float4 v = make_float4(0.f,0.f,0.f,0.f);
            if (gr < N) v = ((const float4*)X)[(size_t)gr*32 + (kk>>2) + c4];
            if (mode & 1){
                v.x = gelu_f(v.x*inScale); v.y = gelu_f(v.y*inScale);
                v.z = gelu_f(v.z*inScale); v.w = gelu_f(v.w*inScale);
            }
            float* d = Xs + r*XS_STRIDE + c4*4;
            d[0] = wmma::__float_to_tf32(v.x);
            d[1] = wmma::__float_to_tf32(v.y);
            d[2] = wmma::__float_to_tf32(v.z);
            d[3] = wmma::__float_to_tf32(v.w);
        }
        #pragma unroll
        for (int i = 0; i < 8; i++){
            int idx = tid + i*256;
            int r = idx >> 5, c4 = idx & 31;
            float4 v = ((const float4*)W)[(size_t)(kk + r)*ldw4 + cb4 + c4];
            float* d = Ws + r*WS_STRIDE + c4*4;
            d[0] = wmma::__float_to_tf32(v.x);
            d[1] = wmma::__float_to_tf32(v.y);
            d[2] = wmma::__float_to_tf32(v.z);
            d[3] = wmma::__float_to_tf32(v.w);
        }
        __syncthreads();

        #pragma unroll
        for (int ks = 0; ks < 8; ks++){
            wmma::fragment<wmma::matrix_a, 16,16,8, wmma::precision::tf32, wmma::row_major> a0, a1;
            wmma::load_matrix_sync(a0, Xs + (wr*32   )*XS_STRIDE + ks*8, XS_STRIDE);
            wmma::load_matrix_sync(a1, Xs + (wr*32+16)*XS_STRIDE + ks*8, XS_STRIDE);
            #pragma unroll
            for (int c = 0; c < 4; c++){
                wmma::fragment<wmma::matrix_b, 16,16,8, wmma::precision::tf32, wmma::row_major> b;
                wmma::load_matrix_sync(b, Ws + (ks*8)*WS_STRIDE + wc*64 + c*16, WS_STRIDE);
                wmma::mma_sync(acc[0][c], a0, b, acc[0][c]);
                wmma::mma_sync(acc[1][c], a1, b, acc[1][c]);
            }
        }
        __syncthreads();
    }

    float* OutS = sm;                     // 128 x WS_STRIDE
    #pragma unroll
    for (int i = 0; i < 2; i++)
        #pragma unroll
        for (int c = 0; c < 4; c++)
            wmma::store_matrix_sync(OutS + (wr*32 + i*16)*WS_STRIDE + wc*64 + c*16,
                                    acc[i][c], WS_STRIDE, wmma::mem_row_major);
    __syncthreads();

    float gate = 1.f, og = 0.f;
    if (mode & 2){ gate = 1.f/(1.f + expf(-skipPtr[0])); og = 1.f - gate; }
    #pragma unroll 1
    for (int i = 0; i < 16; i++){
        int idx = tid + i*256;
        int r = idx >> 5, c4 = idx & 31;
        int gr = bRow + r;
        if (gr >= N) continue;
        const float* o = OutS + r*WS_STRIDE + c4*4;
        float4 bv = ((const float4*)B)[cb4 + c4];
        float4 res;
        res.x = o[0] + bv.x; res.y = o[1] + bv.y;
        res.z = o[2] + bv.z; res.w = o[3] + bv.w;
        if (mode & 2){
            float4 xo = ((const float4*)Xold)[(size_t)gr*32 + c4];
            res.x = gate*res.x + og*xo.x; res.y = gate*res.y + og*xo.y;
            res.z = gate*res.z + og*xo.z; res.w = gate*res.w + og*xo.w;
        }
        ((float4*)Y)[(size_t)gr*ldy4 + cb4 + c4] = res;
        if ((mode & 4) && gr < out2N)
            ((float4*)out2)[(size_t)gr*32 + c4] = res;
    }
}

// ---------------- combined weight prep ----------------
__global__ void prep_weights(const float* __restrict__ k_w, const float* __restrict__ k_b,
                             const float* __restrict__ v_w, const float* __restrict__ v_b,
                             const float* __restrict__ q_w, const float* __restrict__ q_b,
                             const float* __restrict__ a_rel, const float* __restrict__ m_rel)
{
    int fid = blockIdx.x;           // 0..15
    int l = fid >> 3, sid = fid & 7;
    bool paper = sid < 5;
    float* dstBase; int stride, col;
    if (paper){ dstBase = g_wp + l*WP_SZ; stride = 640; col = sid*128; }
    else      { dstBase = g_wa + l*WA_SZ; stride = 384; col = (sid-5)*128; }

    const float *W, *Bi, *R = nullptr;
    switch (sid){
        case 0: W = q_w + (size_t)(l*2+0)*16384; Bi = q_b + (l*2+0)*128; break;
        case 1: W = k_w + (size_t)(l*2+0)*16384; Bi = k_b + (l*2+0)*128; R = a_rel + (size_t)(l*3+1)*4096; break;
        case 2: W = v_w + (size_t)(l*2+0)*16384; Bi = v_b + (l*2+0)*128; R = m_rel + (size_t)(l*3+1)*4096; break;
        case 3: W = k_w + (size_t)(l*2+0)*16384; Bi = k_b + (l*2+0)*128; R = a_rel + (size_t)(l*3+2)*4096; break;
        case 4: W = v_w + (size_t)(l*2+0)*16384; Bi = v_b + (l*2+0)*128; R = m_rel + (size_t)(l*3+2)*4096; break;
        case 5: W = q_w + (size_t)(l*2+1)*16384; Bi = q_b + (l*2+1)*128; break;
        case 6: W = k_w + (size_t)(l*2+1)*16384; Bi = k_b + (l*2+1)*128; R = a_rel + (size_t)(l*3+0)*4096; break;
        default:W = v_w + (size_t)(l*2+1)*16384; Bi = v_b + (l*2+1)*128; R = m_rel + (size_t)(l*3+0)*4096; break;
    }

    int jc = threadIdx.x;
    int i0 = blockIdx.y * 32;
    if (R == nullptr){
        for (int i = i0; i < i0+32; i++) dstBase[i*stride + col + jc] = W[i*128 + jc];
        if (blockIdx.y == 0) dstBase[128*stride + col + jc] = Bi[jc];
        return;
    }
    __shared__ float Rs[4096];
    for (int i = threadIdx.x; i < 4096; i += 128) Rs[i] = R[i];
    __syncthreads();
    int h = jc >> 5, j = jc & 31;
    const float* Rh = Rs + h*1024 + j;
    for (int i = i0; i < i0+32; i++){
        float acc = 0.f;
        #pragma unroll
        for (int d = 0; d < 32; d++) acc += W[i*128 + h*32 + d] * Rh[d*32];
        dstBase[i*stride + col + jc] = acc;
    }
    if (blockIdx.y == 0){
        float accb = 0.f;
        #pragma unroll
        for (int d = 0; d < 32; d++) accb += Bi[h*32 + d] * Rh[d*32];
        dstBase[128*stride + col + jc] = accb;
    }
}

// ---------------- merged CSR build over (type,node) ----------------
__global__ void zero_int_kernel(int* __restrict__ p, int n){
    int i = blockIdx.x*blockDim.x + threadIdx.x;
    if (i < n) p[i] = 0;
}
__global__ void hist3_kernel(const int* __restrict__ d0, const int* __restrict__ d1,
                             const int* __restrict__ d2, int* __restrict__ deg){
    int i = blockIdx.x*blockDim.x + threadIdx.x;
    if (i >= 3*NEDGE) return;
    int t = i / NEDGE, e = i - t*NEDGE;
    int d = (t == 0) ? d0[e] : (t == 1) ? d1[e] : d2[e];
    atomicAdd(&deg[t*NP + d], 1);
}
__global__ void partial_kernel(const int* __restrict__ deg, int* __restrict__ part, int n){
    __shared__ int s[256];
    int tid = threadIdx.x;
    int base = blockIdx.x*1024 + tid*4;
    int sum = 0;
    #pragma unroll
    for (int j = 0; j < 4; j++) if (base + j < n) sum += deg[base + j];
    s[tid] = sum; __syncthreads();
    for (int d = 128; d > 0; d >>= 1){
        if (tid < d) s[tid] += s[tid + d];
        __syncthreads();
    }
    if (tid == 0) part[blockIdx.x] = s[0];
}
__global__ void scan_part_kernel(int* __restrict__ part, int nb){
    __shared__ int s[512];
    int tid = threadIdx.x;
    int v = (tid < nb) ? part[tid] : 0;
    s[tid] = v; __syncthreads();
    for (int d = 1; d < 512; d <<= 1){
        int t = (tid >= d) ? s[tid - d] : 0;
        __syncthreads();
        s[tid] += t;
        __syncthreads();
    }
    if (tid < nb) part[tid] = s[tid] - v;
}
__global__ void offsets_kernel(const int* __restrict__ deg, const int* __restrict__ part,
                               int* __restrict__ off, int* __restrict__ cur, int n, int E){
    __shared__ int s[256];
    int tid = threadIdx.x;
    int base = blockIdx.x*1024 + tid*4;
    int v[4];
    #pragma unroll
    for (int j = 0; j < 4; j++) v[j] = (base + j < n) ? deg[base + j] : 0;
    int tsum = v[0]+v[1]+v[2]+v[3];
    s[tid] = tsum; __syncthreads();
    for (int d = 1; d < 256; d <<= 1){
        int t = (tid >= d) ? s[tid - d] : 0;
        __syncthreads();
        s[tid] += t;
        __syncthreads();
    }
    int run = s[tid] - tsum + part[blockIdx.x];
    #pragma unroll
    for (int j = 0; j < 4; j++){
        if (base + j < n){ off[base + j] = run; cur[base + j] = run; }
        run += v[j];
    }
    if (blockIdx.x == 0 && tid == 0) off[n] = E;
}
__global__ void scatter3_kernel(const int* __restrict__ d0, const int* __restrict__ d1,
                                const int* __restrict__ d2, const int* __restrict__ s0,
                                const int* __restrict__ s1, const int* __restrict__ s2,
                                int* __restrict__ cur, int* __restrict__ srcs){
    int i = blockIdx.x*blockDim.x + threadIdx.x;
    if (i >= 3*NEDGE) return;
    int t = i / NEDGE, e = i - t*NEDGE;
    int d  = (t == 0) ? d0[e] : (t == 1) ? d1[e] : d2[e];
    int sv = (t == 0) ? s0[e] : (t == 1) ? s1[e] : s2[e];
    int pos = atomicAdd(&cur[t*NP + d], 1);
    srcs[pos] = sv;
}

// ---------------- single-pass fused attention aggregation (all dsts) ----------------
__device__ __forceinline__ float4 agg_one(int e0, int e1, const int* __restrict__ srcs,
                                          const float4* __restrict__ buf, int stride4,
                                          int kOff4, int vOff4, float ph, float4 q4, int lane)
{
    float den = 0.f;
    float4 acc = make_float4(0.f,0.f,0.f,0.f);
    for (int base = e0; base < e1; base += 32){
        int m = min(32, e1 - base);
        int myS = (base + lane < e1) ? srcs[base + lane] : 0;
        int j = 0;
        for (; j + 2 <= m; j += 2){
            int sA = __shfl_sync(0xffffffffu, myS, j);
            int sB = __shfl_sync(0xffffffffu, myS, j+1);
            const float4* rA = buf + (size_t)sA*stride4;
            const float4* rB = buf + (size_t)sB*stride4;
            float4 kA = rA[kOff4 + lane];
            float4 vA = rA[vOff4 + lane];
            float4 kB = rB[kOff4 + lane];
            float4 vB = rB[vOff4 + lane];
            float pA = q4.x*kA.x + q4.y*kA.y + q4.z*kA.z + q4.w*kA.w;
            float pB = q4.x*kB.x + q4.y*kB.y + q4.z*kB.z + q4.w*kB.w;
            pA += __shfl_xor_sync(0xffffffffu, pA, 1);
            pB += __shfl_xor_sync(0xffffffffu, pB, 1);
            pA += __shfl_xor_sync(0xffffffffu, pA, 2);
            pB += __shfl_xor_sync(0xffffffffu, pB, 2);
            pA += __shfl_xor_sync(0xffffffffu, pA, 4);
            pB += __shfl_xor_sync(0xffffffffu, pB, 4);
            float eA = __expf(pA * ph);
            float eB = __expf(pB * ph);
            den += eA + eB;
            acc.x += eA*vA.x + eB*vB.x;
            acc.y += eA*vA.y + eB*vB.y;
            acc.z += eA*vA.z + eB*vB.z;
            acc.w += eA*vA.w + eB*vB.w;
        }
        if (j < m){
            int s = __shfl_sync(0xffffffffu, myS, j);
            const float4* row = buf + (size_t)s*stride4;
            float4 k4 = row[kOff4 + lane];
            float4 v4 = row[vOff4 + lane];
            float p = q4.x*k4.x + q4.y*k4.y + q4.z*k4.z + q4.w*k4.w;
            p += __shfl_xor_sync(0xffffffffu, p, 1);
            p += __shfl_xor_sync(0xffffffffu, p, 2);
            p += __shfl_xor_sync(0xffffffffu, p, 4);
            float ex = __expf(p * ph);
            den += ex;
            acc.x += ex*v4.x; acc.y += ex*v4.y;
            acc.z += ex*v4.z; acc.w += ex*v4.w;
        }
    }
    float inv = 1.f/(den + 1e-16f);
    acc.x *= inv; acc.y *= inv; acc.z *= inv; acc.w *= inv;
    return acc;
}

__global__ void aggregate_all(const int* __restrict__ off, const int* __restrict__ srcs,
                              const float4* __restrict__ actp, const float4* __restrict__ acta,
                              const float* __restrict__ prel,   // 12 floats for this layer
                              float4* __restrict__ aggp, float4* __restrict__ agga)
{
    int d = blockIdx.x*8 + (threadIdx.x >> 5);
    int lane = threadIdx.x & 31;
    int h = lane >> 3;
    if (d < NP){
        float4 q4 = actp[(size_t)d*160 + lane];
        float ph0 = prel[0*4 + h] * 0.17677669529663687f;
        float ph2 = prel[2*4 + h] * 0.17677669529663687f;
        float4 res = agg_one(off[d], off[d+1], srcs, acta, 96, 32, 64, ph0, q4, lane);
        float4 r2  = agg_one(off[2*NP+d], off[2*NP+d+1], srcs, actp, 160, 96, 128, ph2, q4, lane);
        res.x += r2.x; res.y += r2.y; res.z += r2.z; res.w += r2.w;
        aggp[(size_t)d*32 + lane] = res;
    } else if (d < NP + NA){
        int da = d - NP;
        float4 q4 = acta[(size_t)da*96 + lane];
        float ph1 = prel[1*4 + h] * 0.17677669529663687f;
        float4 res = agg_one(off[NP+da], off[NP+da+1], srcs, actp, 160, 32, 64, ph1, q4, lane);
        agga[(size_t)da*32 + lane] = res;
    }
}

// ---------------- misc ----------------
__global__ void gather_embed_kernel(const float* __restrict__ tab, const int* __restrict__ idx,
                                    float* __restrict__ out, int n){
    int i = blockIdx.x*blockDim.x + threadIdx.x;
    if (i >= n*32) return;
    int node = i >> 5, c = i & 31;
    int src = idx[node];
    ((float4*)out)[(size_t)node*32 + c] = ((const float4*)tab)[(size_t)src*32 + c];
}

// ---------------- launch ----------------
extern "C" void kernel_launch(void* const* d_in, const int* in_sizes, int n_in,
                              void* d_out, int out_size)
{
    const float* x_paper     = (const float*)d_in[0];
    const int*   author_idx  = (const int*)  d_in[1];
    const float* embed_table = (const float*)d_in[2];
    const float* lin_w       = (const float*)d_in[3];
    const float* lin_b       = (const float*)d_in[4];
    const float* k_w         = (const float*)d_in[5];
    const float* k_b         = (const float*)d_in[6];
    const float* q_w         = (const float*)d_in[7];
    const float* q_b         = (const float*)d_in[8];
    const float* v_w         = (const float*)d_in[9];
    const float* v_b         = (const float*)d_in[10];
    const float* a_rel       = (const float*)d_in[11];
    const float* m_rel       = (const float*)d_in[12];
    const float* p_rel       = (const float*)d_in[13];
    const float* skip        = (const float*)d_in[14];
    const float* a_w         = (const float*)d_in[15];
    const float* a_b         = (const float*)d_in[16];
    const int*   w_src       = (const int*)  d_in[17];
    const int*   w_dst       = (const int*)  d_in[18];
    const int*   r_src       = (const int*)  d_in[19];
    const int*   r_dst       = (const int*)  d_in[20];
    const int*   c_src       = (const int*)  d_in[21];
    const int*   c_dst       = (const int*)  d_in[22];
    float* out = (float*)d_out;

    float *xp,*xa,*actp,*acta,*aggp,*agga,*wp,*wa;
    int *deg,*off,*cur,*srcs,*part;
    cudaGetSymbolAddress((void**)&xp,   g_xp);
    cudaGetSymbolAddress((void**)&xa,   g_xa);
    cudaGetSymbolAddress((void**)&actp, g_actp);
    cudaGetSymbolAddress((void**)&acta, g_acta);
    cudaGetSymbolAddress((void**)&aggp, g_aggp);
    cudaGetSymbolAddress((void**)&agga, g_agga);
    cudaGetSymbolAddress((void**)&wp,   g_wp);
    cudaGetSymbolAddress((void**)&wa,   g_wa);
    cudaGetSymbolAddress((void**)&deg,  g_deg);
    cudaGetSymbolAddress((void**)&off,  g_off);
    cudaGetSymbolAddress((void**)&cur,  g_cur);
    cudaGetSymbolAddress((void**)&srcs, g_srcs);
    cudaGetSymbolAddress((void**)&part, g_part);

    cudaFuncSetAttribute(gemm128_tc, cudaFuncAttributeMaxDynamicSharedMemorySize, SMEM_FLOATS*4);

    const int SMB = SMEM_FLOATS*4;
    const int GP = (NP+127)/128, GA = (NA+127)/128;

    // 1: weight prep ; 2: author embed gather ; 3: paper input projection
    prep_weights<<<dim3(16,4),128>>>(k_w, k_b, v_w, v_b, q_w, q_b, a_rel, m_rel);
    gather_embed_kernel<<<(NA*32+255)/256,256>>>(embed_table, author_idx, xa, NA);
    gemm128_tc<<<dim3(GP,1),256,SMB>>>(x_paper, lin_w, 128, lin_b, xp, 128, nullptr, nullptr,
                                       nullptr, 0, NP, 0, 1.f);

    for (int l = 0; l < 2; l++){
        // 4 (l=0): fused QKV projections  (ncu profiles the 4th launch)
        gemm128_tc<<<dim3(GP,5),256,SMB>>>(xp, wp + l*WP_SZ, 640, wp + l*WP_SZ + 128*640,
                                           actp, 640, nullptr, nullptr, nullptr, 0, NP, 0, 1.f);
        gemm128_tc<<<dim3(GA,3),256,SMB>>>(xa, wa + l*WA_SZ, 384, wa + l*WA_SZ + 128*384,
                                           acta, 384, nullptr, nullptr, nullptr, 0, NA, 0, 1.f);

        if (l == 0){
            // CSR build (needed before first aggregate)
            int n = 3*NP;
            int nb = (n + 1023)/1024;
            zero_int_kernel<<<(n+255)/256,256>>>(deg, n);
            hist3_kernel<<<(3*NEDGE+255)/256,256>>>(w_dst, r_dst, c_dst, deg);
            partial_kernel<<<nb,256>>>(deg, part, n);
            scan_part_kernel<<<1,512>>>(part, nb);
            offsets_kernel<<<nb,256>>>(deg, part, off, cur, n, 3*NEDGE);
            scatter3_kernel<<<(3*NEDGE+255)/256,256>>>(w_dst, r_dst, c_dst, w_src, r_src, c_src, cur, srcs);
        }

        aggregate_all<<<(NP+NA+7)/8,256>>>(off, srcs, (const float4*)actp, (const float4*)acta,
                                           p_rel + l*12, (float4*)aggp, (float4*)agga);

        // update: y = sigmoid(skip)*(gelu(mean)@a_w + a_b) + (1-sigmoid(skip))*x  (+ final out write)
        int modeP = (l == 1) ? 7 : 3, modeA = (l == 1) ? 7 : 3;
        gemm128_tc<<<dim3(GP,1),256,SMB>>>(aggp, a_w + (size_t)(l*2+0)*16384, 128, a_b + (l*2+0)*128,
                                           xp, 128, xp, skip + l*2+0,
                                           out, (l==1)?50000:0, NP, modeP, 0.5f);
        gemm128_tc<<<dim3(GA,1),256,SMB>>>(agga, a_w + (size_t)(l*2+1)*16384, 128, a_b + (l*2+1)*128,
                                           xa, 128, xa, skip + l*2+1,
                                           out + (size_t)50000*128, (l==1)?25000:0, NA, modeA, 1.0f);
    }
}

// round 7
// speedup vs baseline: 3.9534x; 1.8802x over previous
#include <cuda_runtime.h>
#include <cuda_fp16.h>
#include <math.h>
#include <mma.h>

using namespace nvcuda;

#define NP 100000
#define NA 50000
#define NEDGE 250000

#define XSH 136                       // half-element stride for smem tiles
#define OUTS_STRIDE 132               // float stride for epilogue staging
#define SMEM_BYTES (2*128*XSH*2 > 128*OUTS_STRIDE*4 ? 2*128*XSH*2 : 128*OUTS_STRIDE*4)

#define WP_SZ (128*640 + 640)
#define WA_SZ (128*384 + 384)

// ---------------- scratch ----------------
__device__ float  g_xp[NP*128];
__device__ float  g_xa[NA*128];
__device__ __half g_actp[(size_t)NP*640];   // [q k1 v1 k2 v2]  (fp16)
__device__ __half g_acta[(size_t)NA*384];   // [q k0 v0]        (fp16)
__device__ float  g_aggp[NP*128];
__device__ float  g_agga[NA*128];
__device__ float  g_wp[2*WP_SZ];
__device__ float  g_wa[2*WA_SZ];
__device__ int    g_deg[3*NP];
__device__ int    g_off[3*NP+1];
__device__ int    g_cur[3*NP];
__device__ int    g_srcs[3*NEDGE];
__device__ int    g_part[512];

__device__ __forceinline__ float gelu_f(float x){
    return 0.5f*x*(1.0f + erff(x*0.70710678118654752f));
}
__device__ __forceinline__ float4 h4f(uint2 u){
    __half2 a = *(__half2*)&u.x, b = *(__half2*)&u.y;
    float2 fa = __half22float2(a), fb = __half22float2(b);
    return make_float4(fa.x, fa.y, fb.x, fb.y);
}

// ---------------- fp16 tensor-core GEMM: [N,128] x [128,Nw] ----------------
// warp subtile 32x64 ; K=128 in one smem pass
// mode bit0: gelu(inScale*x) on input ; bit1: blend y=g*(acc+b)+(1-g)*Xold
// mode bit2: also write rows < out2N to out2 (fp32, ld 128) ; bit3: Y is fp16
__global__ void __launch_bounds__(256, 2)
gemm128_tc(const float* __restrict__ X, const float* __restrict__ W, int ldw,
           const float* __restrict__ B, void* __restrict__ Y, int ldy,
           const float* __restrict__ Xold, const float* __restrict__ skipPtr,
           float* __restrict__ out2, int out2N,
           int N, int mode, float inScale)
{
    extern __shared__ float sm[];
    __half* Xs = (__half*)sm;                 // 128 x XSH (128 cols used)
    __half* Ws = (__half*)sm + 128*XSH;       // 128 x XSH (128 cols used)
    const int tid  = threadIdx.x;
    const int warp = tid >> 5;
    const int wr   = warp >> 1;               // row group (32 rows)
    const int wc   = warp & 1;                // col group (64 cols)
    const int bRow = blockIdx.x * 128;
    const int colBase = blockIdx.y * 128;
    const int ldw4 = ldw >> 2, cb4 = colBase >> 2;

    wmma::fragment<wmma::accumulator, 16,16,16, float> acc[2][4];
    #pragma unroll
    for (int i = 0; i < 2; i++)
        #pragma unroll
        for (int c = 0; c < 4; c++) wmma::fill_fragment(acc[i][c], 0.f);

    // load X tile [bRow..+128) x [0,128)  -> fp16
    #pragma unroll
    for (int i = 0; i < 16; i++){
        int idx = tid + i*256;                // 4096 float4
        int r = idx >> 5, c4 = idx & 31;
        int gr = bRow + r;
        float4 v = make_float4(0.f,0.f,0.f,0.f);
        if (gr < N) v = ((const float4*)X)[(size_t)gr*32 + c4];
        if (mode & 1){
            v.x = gelu_f(v.x*inScale); v.y = gelu_f(v.y*inScale);
            v.z = gelu_f(v.z*inScale); v.w = gelu_f(v.w*inScale);
        }
        __half2 h0 = __floats2half2_rn(v.x, v.y);
        __half2 h1 = __floats2half2_rn(v.z, v.w);
        __half2* d = (__half2*)(Xs + r*XSH + c4*4);
        d[0] = h0; d[1] = h1;
    }
    // load W tile [0,128) x [colBase..+128) -> fp16
    #pragma unroll
    for (int i = 0; i < 16; i++){
        int idx = tid + i*256;
        int r = idx >> 5, c4 = idx & 31;
        float4 v = ((const float4*)W)[(size_t)r*ldw4 + cb4 + c4];
        __half2 h0 = __floats2half2_rn(v.x, v.y);
        __half2 h1 = __floats2half2_rn(v.z, v.w);
        __half2* d = (__half2*)(Ws + r*XSH + c4*4);
        d[0] = h0; d[1] = h1;
    }
    __syncthreads();

    #pragma unroll
    for (int ks = 0; ks < 8; ks++){
        wmma::fragment<wmma::matrix_a, 16,16,16, __half, wmma::row_major> a0, a1;
        wmma::load_matrix_sync(a0, Xs + (wr*32   )*XSH + ks*16, XSH);
        wmma::load_matrix_sync(a1, Xs + (wr*32+16)*XSH + ks*16, XSH);
        #pragma unroll
        for (int c = 0; c < 4; c++){
            wmma::fragment<wmma::matrix_b, 16,16,16, __half, wmma::row_major> b;
            wmma::load_matrix_sync(b, Ws + (ks*16)*XSH + wc*64 + c*16, XSH);
            wmma::mma_sync(acc[0][c], a0, b, acc[0][c]);
            wmma::mma_sync(acc[1][c], a1, b, acc[1][c]);
        }
    }
    __syncthreads();

    float* OutS = sm;                         // 128 x OUTS_STRIDE floats
    #pragma unroll
    for (int i = 0; i < 2; i++)
        #pragma unroll
        for (int c = 0; c < 4; c++)
            wmma::store_matrix_sync(OutS + (wr*32 + i*16)*OUTS_STRIDE + wc*64 + c*16,
                                    acc[i][c], OUTS_STRIDE, wmma::mem_row_major);
    __syncthreads();

    float gate = 1.f, og = 0.f;
    if (mode & 2){ gate = 1.f/(1.f + expf(-skipPtr[0])); og = 1.f - gate; }
    #pragma unroll 1
    for (int i = 0; i < 16; i++){
        int idx = tid + i*256;
        int r = idx >> 5, c4 = idx & 31;
        int gr = bRow + r;
        if (gr >= N) continue;
        const float* o = OutS + r*OUTS_STRIDE + c4*4;
        float4 bv = ((const float4*)B)[cb4 + c4];
        float4 res;
        res.x = o[0] + bv.x; res.y = o[1] + bv.y;
        res.z = o[2] + bv.z; res.w = o[3] + bv.w;
        if (mode & 2){
            float4 xo = ((const float4*)Xold)[(size_t)gr*32 + c4];
            res.x = gate*res.x + og*xo.x; res.y = gate*res.y + og*xo.y;
            res.z = gate*res.z + og*xo.z; res.w = gate*res.w + og*xo.w;
        }
        if (mode & 8){
            __half* Yh = (__half*)Y;
            __half2 h0 = __floats2half2_rn(res.x, res.y);
            __half2 h1 = __floats2half2_rn(res.z, res.w);
            __half2* d = (__half2*)(Yh + (size_t)gr*ldy + colBase + c4*4);
            d[0] = h0; d[1] = h1;
        } else {
            ((float4*)Y)[(size_t)gr*(ldy>>2) + cb4 + c4] = res;
        }
        if ((mode & 4) && gr < out2N)
            ((float4*)out2)[(size_t)gr*32 + c4] = res;
    }
}

// ---------------- combined weight prep (fp32 out; GEMM converts) ----------------
__global__ void prep_weights(const float* __restrict__ k_w, const float* __restrict__ k_b,
                             const float* __restrict__ v_w, const float* __restrict__ v_b,
                             const float* __restrict__ q_w, const float* __restrict__ q_b,
                             const float* __restrict__ a_rel, const float* __restrict__ m_rel)
{
    int fid = blockIdx.x;           // 0..15
    int l = fid >> 3, sid = fid & 7;
    bool paper = sid < 5;
    float* dstBase; int stride, col;
    if (paper){ dstBase = g_wp + l*WP_SZ; stride = 640; col = sid*128; }
    else      { dstBase = g_wa + l*WA_SZ; stride = 384; col = (sid-5)*128; }

    const float *W, *Bi, *R = nullptr;
    switch (sid){
        case 0: W = q_w + (size_t)(l*2+0)*16384; Bi = q_b + (l*2+0)*128; break;
        case 1: W = k_w + (size_t)(l*2+0)*16384; Bi = k_b + (l*2+0)*128; R = a_rel + (size_t)(l*3+1)*4096; break;
        case 2: W = v_w + (size_t)(l*2+0)*16384; Bi = v_b + (l*2+0)*128; R = m_rel + (size_t)(l*3+1)*4096; break;
        case 3: W = k_w + (size_t)(l*2+0)*16384; Bi = k_b + (l*2+0)*128; R = a_rel + (size_t)(l*3+2)*4096; break;
        case 4: W = v_w + (size_t)(l*2+0)*16384; Bi = v_b + (l*2+0)*128; R = m_rel + (size_t)(l*3+2)*4096; break;
        case 5: W = q_w + (size_t)(l*2+1)*16384; Bi = q_b + (l*2+1)*128; break;
        case 6: W = k_w + (size_t)(l*2+1)*16384; Bi = k_b + (l*2+1)*128; R = a_rel + (size_t)(l*3+0)*4096; break;
        default:W = v_w + (size_t)(l*2+1)*16384; Bi = v_b + (l*2+1)*128; R = m_rel + (size_t)(l*3+0)*4096; break;
    }

    int jc = threadIdx.x;
    int i0 = blockIdx.y * 32;
    if (R == nullptr){
        for (int i = i0; i < i0+32; i++) dstBase[i*stride + col + jc] = W[i*128 + jc];
        if (blockIdx.y == 0) dstBase[128*stride + col + jc] = Bi[jc];
        return;
    }
    __shared__ float Rs[4096];
    for (int i = threadIdx.x; i < 4096; i += 128) Rs[i] = R[i];
    __syncthreads();
    int h = jc >> 5, j = jc & 31;
    const float* Rh = Rs + h*1024 + j;
    for (int i = i0; i < i0+32; i++){
        float acc = 0.f;
        #pragma unroll
        for (int d = 0; d < 32; d++) acc += W[i*128 + h*32 + d] * Rh[d*32];
        dstBase[i*stride + col + jc] = acc;
    }
    if (blockIdx.y == 0){
        float accb = 0.f;
        #pragma unroll
        for (int d = 0; d < 32; d++) accb += Bi[h*32 + d] * Rh[d*32];
        dstBase[128*stride + col + jc] = accb;
    }
}

// ---------------- merged CSR build over (type,node) ----------------
__global__ void zero_int_kernel(int* __restrict__ p, int n){
    int i = blockIdx.x*blockDim.x + threadIdx.x;
    if (i < n) p[i] = 0;
}
__global__ void hist3_kernel(const int* __restrict__ d0, const int* __restrict__ d1,
                             const int* __restrict__ d2, int* __restrict__ deg){
    int i = blockIdx.x*blockDim.x + threadIdx.x;
    if (i >= 3*NEDGE) return;
    int t = i / NEDGE, e = i - t*NEDGE;
    int d = (t == 0) ? d0[e] : (t == 1) ? d1[e] : d2[e];
    atomicAdd(&deg[t*NP + d], 1);
}
__global__ void partial_kernel(const int* __restrict__ deg, int* __restrict__ part, int n){
    __shared__ int s[256];
    int tid = threadIdx.x;
    int base = blockIdx.x*1024 + tid*4;
    int sum = 0;
    #pragma unroll
    for (int j = 0; j < 4; j++) if (base + j < n) sum += deg[base + j];
    s[tid] = sum; __syncthreads();
    for (int d = 128; d > 0; d >>= 1){
        if (tid < d) s[tid] += s[tid + d];
        __syncthreads();
    }
    if (tid == 0) part[blockIdx.x] = s[0];
}
__global__ void scan_part_kernel(int* __restrict__ part, int nb){
    __shared__ int s[512];
    int tid = threadIdx.x;
    int v = (tid < nb) ? part[tid] : 0;
    s[tid] = v; __syncthreads();
    for (int d = 1; d < 512; d <<= 1){
        int t = (tid >= d) ? s[tid - d] : 0;
        __syncthreads();
        s[tid] += t;
        __syncthreads();
    }
    if (tid < nb) part[tid] = s[tid] - v;
}
__global__ void offsets_kernel(const int* __restrict__ deg, const int* __restrict__ part,
                               int* __restrict__ off, int* __restrict__ cur, int n, int E){
    __shared__ int s[256];
    int tid = threadIdx.x;
    int base = blockIdx.x*1024 + tid*4;
    int v[4];
    #pragma unroll
    for (int j = 0; j < 4; j++) v[j] = (base + j < n) ? deg[base + j] : 0;
    int tsum = v[0]+v[1]+v[2]+v[3];
    s[tid] = tsum; __syncthreads();
    for (int d = 1; d < 256; d <<= 1){
        int t = (tid >= d) ? s[tid - d] : 0;
        __syncthreads();
        s[tid] += t;
        __syncthreads();
    }
    int run = s[tid] - tsum + part[blockIdx.x];
    #pragma unroll
    for (int j = 0; j < 4; j++){
        if (base + j < n){ off[base + j] = run; cur[base + j] = run; }
        run += v[j];
    }
    if (blockIdx.x == 0 && tid == 0) off[n] = E;
}
__global__ void scatter3_kernel(const int* __restrict__ d0, const int* __restrict__ d1,
                                const int* __restrict__ d2, const int* __restrict__ s0,
                                const int* __restrict__ s1, const int* __restrict__ s2,
                                int* __restrict__ cur, int* __restrict__ srcs){
    int i = blockIdx.x*blockDim.x + threadIdx.x;
    if (i >= 3*NEDGE) return;
    int t = i / NEDGE, e = i - t*NEDGE;
    int d  = (t == 0) ? d0[e] : (t == 1) ? d1[e] : d2[e];
    int sv = (t == 0) ? s0[e] : (t == 1) ? s1[e] : s2[e];
    int pos = atomicAdd(&cur[t*NP + d], 1);
    srcs[pos] = sv;
}

// ---------------- single-pass fused attention aggregation (fp16 gathers) ----------------
__device__ __forceinline__ float4 agg_one(int e0, int e1, const int* __restrict__ srcs,
                                          const uint2* __restrict__ buf, int stride4,
                                          int kOff4, int vOff4, float ph, float4 q4, int lane)
{
    float den = 0.f;
    float4 acc = make_float4(0.f,0.f,0.f,0.f);
    for (int base = e0; base < e1; base += 32){
        int m = min(32, e1 - base);
        int myS = (base + lane < e1) ? srcs[base + lane] : 0;
        int j = 0;
        for (; j + 2 <= m; j += 2){
            int sA = __shfl_sync(0xffffffffu, myS, j);
            int sB = __shfl_sync(0xffffffffu, myS, j+1);
            const uint2* rA = buf + (size_t)sA*stride4;
            const uint2* rB = buf + (size_t)sB*stride4;
            float4 kA = h4f(rA[kOff4 + lane]);
            float4 vA = h4f(rA[vOff4 + lane]);
            float4 kB = h4f(rB[kOff4 + lane]);
            float4 vB = h4f(rB[vOff4 + lane]);
            float pA = q4.x*kA.x + q4.y*kA.y + q4.z*kA.z + q4.w*kA.w;
            float pB = q4.x*kB.x + q4.y*kB.y + q4.z*kB.z + q4.w*kB.w;
            pA += __shfl_xor_sync(0xffffffffu, pA, 1);
            pB += __shfl_xor_sync(0xffffffffu, pB, 1);
            pA += __shfl_xor_sync(0xffffffffu, pA, 2);
            pB += __shfl_xor_sync(0xffffffffu, pB, 2);
            pA += __shfl_xor_sync(0xffffffffu, pA, 4);
            pB += __shfl_xor_sync(0xffffffffu, pB, 4);
            float eA = __expf(pA * ph);
            float eB = __expf(pB * ph);
            den += eA + eB;
            acc.x += eA*vA.x + eB*vB.x;
            acc.y += eA*vA.y + eB*vB.y;
            acc.z += eA*vA.z + eB*vB.z;
            acc.w += eA*vA.w + eB*vB.w;
        }
        if (j < m){
            int s = __shfl_sync(0xffffffffu, myS, j);
            const uint2* row = buf + (size_t)s*stride4;
            float4 k4 = h4f(row[kOff4 + lane]);
            float4 v4 = h4f(row[vOff4 + lane]);
            float p = q4.x*k4.x + q4.y*k4.y + q4.z*k4.z + q4.w*k4.w;
            p += __shfl_xor_sync(0xffffffffu, p, 1);
            p += __shfl_xor_sync(0xffffffffu, p, 2);
            p += __shfl_xor_sync(0xffffffffu, p, 4);
            float ex = __expf(p * ph);
            den += ex;
            acc.x += ex*v4.x; acc.y += ex*v4.y;
            acc.z += ex*v4.z; acc.w += ex*v4.w;
        }
    }
    float inv = 1.f/(den + 1e-16f);
    acc.x *= inv; acc.y *= inv; acc.z *= inv; acc.w *= inv;
    return acc;
}

__global__ void aggregate_all(const int* __restrict__ off, const int* __restrict__ srcs,
                              const uint2* __restrict__ actp, const uint2* __restrict__ acta,
                              const float* __restrict__ prel,   // 12 floats for this layer
                              float4* __restrict__ aggp, float4* __restrict__ agga)
{
    int d = blockIdx.x*8 + (threadIdx.x >> 5);
    int lane = threadIdx.x & 31;
    int h = lane >> 3;
    if (d < NP){
        float4 q4 = h4f(actp[(size_t)d*160 + lane]);
        float ph0 = prel[0*4 + h] * 0.17677669529663687f;
        float ph2 = prel[2*4 + h] * 0.17677669529663687f;
        float4 res = agg_one(off[d], off[d+1], srcs, acta, 96, 32, 64, ph0, q4, lane);
        float4 r2  = agg_one(off[2*NP+d], off[2*NP+d+1], srcs, actp, 160, 96, 128, ph2, q4, lane);
        res.x += r2.x; res.y += r2.y; res.z += r2.z; res.w += r2.w;
        aggp[(size_t)d*32 + lane] = res;
    } else if (d < NP + NA){
        int da = d - NP;
        float4 q4 = h4f(acta[(size_t)da*96 + lane]);
        float ph1 = prel[1*4 + h] * 0.17677669529663687f;
        float4 res = agg_one(off[NP+da], off[NP+da+1], srcs, actp, 160, 32, 64, ph1, q4, lane);
        agga[(size_t)da*32 + lane] = res;
    }
}

// ---------------- misc ----------------
__global__ void gather_embed_kernel(const float* __restrict__ tab, const int* __restrict__ idx,
                                    float* __restrict__ out, int n){
    int i = blockIdx.x*blockDim.x + threadIdx.x;
    if (i >= n*32) return;
    int node = i >> 5, c = i & 31;
    int src = idx[node];
    ((float4*)out)[(size_t)node*32 + c] = ((const float4*)tab)[(size_t)src*32 + c];
}

// ---------------- launch ----------------
extern "C" void kernel_launch(void* const* d_in, const int* in_sizes, int n_in,
                              void* d_out, int out_size)
{
    const float* x_paper     = (const float*)d_in[0];
    const int*   author_idx  = (const int*)  d_in[1];
    const float* embed_table = (const float*)d_in[2];
    const float* lin_w       = (const float*)d_in[3];
    const float* lin_b       = (const float*)d_in[4];
    const float* k_w         = (const float*)d_in[5];
    const float* k_b         = (const float*)d_in[6];
    const float* q_w         = (const float*)d_in[7];
    const float* q_b         = (const float*)d_in[8];
    const float* v_w         = (const float*)d_in[9];
    const float* v_b         = (const float*)d_in[10];
    const float* a_rel       = (const float*)d_in[11];
    const float* m_rel       = (const float*)d_in[12];
    const float* p_rel       = (const float*)d_in[13];
    const float* skip        = (const float*)d_in[14];
    const float* a_w         = (const float*)d_in[15];
    const float* a_b         = (const float*)d_in[16];
    const int*   w_src       = (const int*)  d_in[17];
    const int*   w_dst       = (const int*)  d_in[18];
    const int*   r_src       = (const int*)  d_in[19];
    const int*   r_dst       = (const int*)  d_in[20];
    const int*   c_src       = (const int*)  d_in[21];
    const int*   c_dst       = (const int*)  d_in[22];
    float* out = (float*)d_out;

    float *xp,*xa,*aggp,*agga,*wp,*wa;
    __half *actp,*acta;
    int *deg,*off,*cur,*srcs,*part;
    cudaGetSymbolAddress((void**)&xp,   g_xp);
    cudaGetSymbolAddress((void**)&xa,   g_xa);
    cudaGetSymbolAddress((void**)&actp, g_actp);
    cudaGetSymbolAddress((void**)&acta, g_acta);
    cudaGetSymbolAddress((void**)&aggp, g_aggp);
    cudaGetSymbolAddress((void**)&agga, g_agga);
    cudaGetSymbolAddress((void**)&wp,   g_wp);
    cudaGetSymbolAddress((void**)&wa,   g_wa);
    cudaGetSymbolAddress((void**)&deg,  g_deg);
    cudaGetSymbolAddress((void**)&off,  g_off);
    cudaGetSymbolAddress((void**)&cur,  g_cur);
    cudaGetSymbolAddress((void**)&srcs, g_srcs);
    cudaGetSymbolAddress((void**)&part, g_part);

    cudaFuncSetAttribute(gemm128_tc, cudaFuncAttributeMaxDynamicSharedMemorySize, SMEM_BYTES);

    const int SMB = SMEM_BYTES;
    const int GP = (NP+127)/128, GA = (NA+127)/128;

    // 1: weight prep ; 2: author embed gather ; 3: paper input projection
    prep_weights<<<dim3(16,4),128>>>(k_w, k_b, v_w, v_b, q_w, q_b, a_rel, m_rel);
    gather_embed_kernel<<<(NA*32+255)/256,256>>>(embed_table, author_idx, xa, NA);
    gemm128_tc<<<dim3(GP,1),256,SMB>>>(x_paper, lin_w, 128, lin_b, xp, 128, nullptr, nullptr,
                                       nullptr, 0, NP, 0, 1.f);

    for (int l = 0; l < 2; l++){
        // 4 (l=0): fused QKV projections -> fp16 act buffers  (ncu profiles the 4th launch)
        gemm128_tc<<<dim3(GP,5),256,SMB>>>(xp, wp + l*WP_SZ, 640, wp + l*WP_SZ + 128*640,
                                           actp, 640, nullptr, nullptr, nullptr, 0, NP, 8, 1.f);
        gemm128_tc<<<dim3(GA,3),256,SMB>>>(xa, wa + l*WA_SZ, 384, wa + l*WA_SZ + 128*384,
                                           acta, 384, nullptr, nullptr, nullptr, 0, NA, 8, 1.f);

        if (l == 0){
            // CSR build (needed before first aggregate)
            int n = 3*NP;
            int nb = (n + 1023)/1024;
            zero_int_kernel<<<(n+255)/256,256>>>(deg, n);
            hist3_kernel<<<(3*NEDGE+255)/256,256>>>(w_dst, r_dst, c_dst, deg);
            partial_kernel<<<nb,256>>>(deg, part, n);
            scan_part_kernel<<<1,512>>>(part, nb);
            offsets_kernel<<<nb,256>>>(deg, part, off, cur, n, 3*NEDGE);
            scatter3_kernel<<<(3*NEDGE+255)/256,256>>>(w_dst, r_dst, c_dst, w_src, r_src, c_src, cur, srcs);
        }

        aggregate_all<<<(NP+NA+7)/8,256>>>(off, srcs, (const uint2*)actp, (const uint2*)acta,
                                           p_rel + l*12, (float4*)aggp, (float4*)agga);

        // update: y = sigmoid(skip)*(gelu(mean)@a_w + a_b) + (1-sigmoid(skip))*x  (+ final out write)
        int modeP = (l == 1) ? 7 : 3, modeA = (l == 1) ? 7 : 3;
        gemm128_tc<<<dim3(GP,1),256,SMB>>>(aggp, a_w + (size_t)(l*2+0)*16384, 128, a_b + (l*2+0)*128,
                                           xp, 128, xp, skip + l*2+0,
                                           out, (l==1)?50000:0, NP, modeP, 0.5f);
        gemm128_tc<<<dim3(GA,1),256,SMB>>>(agga, a_w + (size_t)(l*2+1)*16384, 128, a_b + (l*2+1)*128,
                                           xa, 128, xa, skip + l*2+1,
                                           out + (size_t)50000*128, (l==1)?25000:0, NA, modeA, 1.0f);
    }
}

// round 10
// speedup vs baseline: 4.3206x; 1.0929x over previous
#include <cuda_runtime.h>
#include <cuda_fp16.h>
#include <stdint.h>
#include <math.h>

#define NP 100000
#define NA 50000
#define NEDGE 250000
#define XSH 136                       // halves per smem tile row
#define SMEM_BYTES (2*128*XSH*2)      // 69632

// ---------------- scratch ----------------
__device__ __half g_xp[(size_t)NP*128];
__device__ __half g_xa[(size_t)NA*128];
__device__ __half g_actp[(size_t)NP*640];   // [q k1 v1 k2 v2]
__device__ __half g_acta[(size_t)NA*384];   // [q k0 v0]
__device__ __half g_aggp[(size_t)NP*128];   // gelu'd, fp16
__device__ __half g_agga[(size_t)NA*128];
__device__ __half g_wph[2][128*640];
__device__ float  g_bp[2][640];
__device__ __half g_wah[2][128*384];
__device__ float  g_ba[2][384];
__device__ __half g_wlinh[128*128];
__device__ __half g_awh[4][128*128];
__device__ int    g_deg[3*NP];
__device__ int    g_off[3*NP+1];
__device__ int    g_cur[3*NP];
__device__ int    g_srcs[3*NEDGE];
__device__ int    g_part[512];

__device__ __forceinline__ float gelu_f(float x){
    return 0.5f*x*(1.0f + erff(x*0.70710678118654752f));
}
__device__ __forceinline__ float4 h4f(uint2 u){
    __half2 a = *(__half2*)&u.x, b = *(__half2*)&u.y;
    float2 fa = __half22float2(a), fb = __half22float2(b);
    return make_float4(fa.x, fa.y, fb.x, fb.y);
}
__device__ __forceinline__ unsigned smem_u32(const void* p){
    unsigned r;
    asm("{ .reg .u64 t; cvta.to.shared.u64 t, %1; cvt.u32.u64 %0, t; }" : "=r"(r) : "l"(p));
    return r;
}
__device__ __forceinline__ void ldmA(unsigned a[4], unsigned addr){
    asm volatile("ldmatrix.sync.aligned.m8n8.x4.shared.b16 {%0,%1,%2,%3}, [%4];"
        : "=r"(a[0]),"=r"(a[1]),"=r"(a[2]),"=r"(a[3]) : "r"(addr));
}
__device__ __forceinline__ void ldmBT(unsigned b[4], unsigned addr){
    asm volatile("ldmatrix.sync.aligned.m8n8.x4.trans.shared.b16 {%0,%1,%2,%3}, [%4];"
        : "=r"(b[0]),"=r"(b[1]),"=r"(b[2]),"=r"(b[3]) : "r"(addr));
}
__device__ __forceinline__ void mma16816(float d[4], const unsigned a[4], const unsigned* b){
    asm volatile("mma.sync.aligned.m16n8k16.row.col.f32.f16.f16.f32 "
        "{%0,%1,%2,%3},{%4,%5,%6,%7},{%8,%9},{%0,%1,%2,%3};"
        : "+f"(d[0]),"+f"(d[1]),"+f"(d[2]),"+f"(d[3])
        : "r"(a[0]),"r"(a[1]),"r"(a[2]),"r"(a[3]),"r"(b[0]),"r"(b[1]));
}

// ---------------- fp16 mma GEMM: [N,128] x [128,Nw], register epilogue ----------------
// mode bit0: X is fp32 ; bit1: blend y=g*(acc+b)+(1-g)*Xold ; bit2: write out2 fp32 ; bit3: skip Y
__global__ void __launch_bounds__(256, 2)
gemm_mma(const void* __restrict__ Xv, const __half* __restrict__ W, int ldw,
         const float* __restrict__ B, __half* __restrict__ Y, int ldy,
         const __half* __restrict__ Xold, const float* __restrict__ skipPtr,
         float* __restrict__ out2, int out2N,
         int N, int mode)
{
    extern __shared__ __half sh[];
    __half* Xs = sh;
    __half* Ws = sh + 128*XSH;
    const int tid = threadIdx.x, warp = tid>>5, lane = tid&31;
    const int wr = warp>>1, wc = warp&1;
    const int bRow = blockIdx.x*128, colBase = blockIdx.y*128;

    if (mode & 1){
        const float* Xf = (const float*)Xv;
        #pragma unroll
        for (int i = 0; i < 16; i++){
            int idx = tid + i*256;           // 4096 float4s
            int r = idx>>5, c4 = idx&31;
            int gr = bRow + r;
            float4 v = (gr < N) ? ((const float4*)Xf)[(size_t)gr*32 + c4]
                                : make_float4(0.f,0.f,0.f,0.f);
            __half2 h0 = __floats2half2_rn(v.x,v.y), h1 = __floats2half2_rn(v.z,v.w);
            uint2 u; u.x = *(unsigned*)&h0; u.y = *(unsigned*)&h1;
            *(uint2*)(Xs + r*XSH + c4*4) = u;
        }
    } else {
        const __half* Xh = (const __half*)Xv;
        #pragma unroll
        for (int i = 0; i < 8; i++){
            int idx = tid + i*256;           // 2048 16B chunks
            int r = idx>>4, ch = idx&15;
            int gr = bRow + r;
            uint4 v = make_uint4(0u,0u,0u,0u);
            if (gr < N) v = *(const uint4*)(Xh + (size_t)gr*128 + ch*8);
            *(uint4*)(Xs + r*XSH + ch*8) = v;
        }
    }
    #pragma unroll
    for (int i = 0; i < 8; i++){
        int idx = tid + i*256;
        int r = idx>>4, ch = idx&15;
        uint4 v = *(const uint4*)(W + (size_t)r*ldw + colBase + ch*8);
        *(uint4*)(Ws + r*XSH + ch*8) = v;
    }
    __syncthreads();

    float d[2][8][4];
    #pragma unroll
    for (int mi=0;mi<2;mi++)
        #pragma unroll
        for (int ni=0;ni<8;ni++)
            #pragma unroll
            for (int k=0;k<4;k++) d[mi][ni][k]=0.f;

    unsigned xA0 = smem_u32(Xs) + (unsigned)(((wr*32 + (lane&15))*XSH + (lane>>4)*8)*2);
    unsigned xA1 = xA0 + 16*XSH*2;
    unsigned wB  = smem_u32(Ws) + (unsigned)((((lane&15))*XSH + wc*64 + (lane>>4)*8)*2);

    #pragma unroll
    for (int ks = 0; ks < 8; ks++){
        unsigned a0[4], a1[4];
        ldmA(a0, xA0 + ks*32);
        ldmA(a1, xA1 + ks*32);
        #pragma unroll
        for (int nt = 0; nt < 4; nt++){
            unsigned bb[4];
            ldmBT(bb, wB + (unsigned)(ks*16*XSH*2) + nt*32);
            mma16816(d[0][2*nt],   a0, bb);
            mma16816(d[0][2*nt+1], a0, bb+2);
            mma16816(d[1][2*nt],   a1, bb);
            mma16816(d[1][2*nt+1], a1, bb+2);
        }
    }

    float gate = 1.f, og = 0.f;
    if (mode & 2){ gate = 1.f/(1.f + expf(-skipPtr[0])); og = 1.f - gate; }
    const int g = lane>>2, t2 = (lane&3)*2;
    float2 bv[8];
    #pragma unroll
    for (int ni=0;ni<8;ni++) bv[ni] = *(const float2*)(B + colBase + wc*64 + ni*8 + t2);

    #pragma unroll
    for (int mi=0;mi<2;mi++){
        int rbase = bRow + wr*32 + mi*16 + g;
        #pragma unroll
        for (int ni=0;ni<8;ni++){
            int c = colBase + wc*64 + ni*8 + t2;
            #pragma unroll
            for (int h=0; h<2; h++){
                int r = rbase + h*8;
                if (r >= N) continue;
                float rx = d[mi][ni][2*h]   + bv[ni].x;
                float ry = d[mi][ni][2*h+1] + bv[ni].y;
                if (mode & 2){
                    __half2 xo = *(const __half2*)(Xold + (size_t)r*128 + c);
                    float2 xf = __half22float2(xo);
                    rx = gate*rx + og*xf.x;
                    ry = gate*ry + og*xf.y;
                }
                if (!(mode & 8)){
                    __half2 hh = __floats2half2_rn(rx, ry);
                    *(__half2*)(Y + (size_t)r*ldy + c) = hh;
                }
                if ((mode & 4) && r < out2N)
                    *(float2*)(out2 + (size_t)r*128 + c) = make_float2(rx, ry);
            }
        }
    }
}

// ---------------- weight prep: fold relation transforms, emit fp16 ----------------
__global__ void prep_weights(const float* __restrict__ k_w, const float* __restrict__ k_b,
                             const float* __restrict__ v_w, const float* __restrict__ v_b,
                             const float* __restrict__ q_w, const float* __restrict__ q_b,
                             const float* __restrict__ a_rel, const float* __restrict__ m_rel,
                             const float* __restrict__ lin_w, const float* __restrict__ a_w)
{
    int fid = blockIdx.x;           // 0..20
    int jc = threadIdx.x;
    int i0 = blockIdx.y * 32;

    if (fid >= 16){
        const float* W = (fid == 16) ? lin_w : a_w + (size_t)(fid-17)*16384;
        __half* D = (fid == 16) ? g_wlinh : g_awh[fid-17];
        for (int i = i0; i < i0+32; i++) D[i*128 + jc] = __float2half(W[i*128 + jc]);
        return;
    }

    int l = fid >> 3, sid = fid & 7;
    bool paper = sid < 5;
    __half* dstW; float* dstB; int stride, col;
    if (paper){ dstW = g_wph[l]; dstB = g_bp[l]; stride = 640; col = sid*128; }
    else      { dstW = g_wah[l]; dstB = g_ba[l]; stride = 384; col = (sid-5)*128; }

    const float *W, *Bi, *R = nullptr;
    switch (sid){
        case 0: W = q_w + (size_t)(l*2+0)*16384; Bi = q_b + (l*2+0)*128; break;
        case 1: W = k_w + (size_t)(l*2+0)*16384; Bi = k_b + (l*2+0)*128; R = a_rel + (size_t)(l*3+1)*4096; break;
        case 2: W = v_w + (size_t)(l*2+0)*16384; Bi = v_b + (l*2+0)*128; R = m_rel + (size_t)(l*3+1)*4096; break;
        case 3: W = k_w + (size_t)(l*2+0)*16384; Bi = k_b + (l*2+0)*128; R = a_rel + (size_t)(l*3+2)*4096; break;
        case 4: W = v_w + (size_t)(l*2+0)*16384; Bi = v_b + (l*2+0)*128; R = m_rel + (size_t)(l*3+2)*4096; break;
        case 5: W = q_w + (size_t)(l*2+1)*16384; Bi = q_b + (l*2+1)*128; break;
        case 6: W = k_w + (size_t)(l*2+1)*16384; Bi = k_b + (l*2+1)*128; R = a_rel + (size_t)(l*3+0)*4096; break;
        default:W = v_w + (size_t)(l*2+1)*16384; Bi = v_b + (l*2+1)*128; R = m_rel + (size_t)(l*3+0)*4096; break;
    }

    if (R == nullptr){
        for (int i = i0; i < i0+32; i++) dstW[i*stride + col + jc] = __float2half(W[i*128 + jc]);
        if (blockIdx.y == 0) dstB[col + jc] = Bi[jc];
        return;
    }
    __shared__ float Rs[4096];
    for (int i = threadIdx.x; i < 4096; i += 128) Rs[i] = R[i];
    __syncthreads();
    int h = jc >> 5, j = jc & 31;
    const float* Rh = Rs + h*1024 + j;
    for (int i = i0; i < i0+32; i++){
        float acc = 0.f;
        #pragma unroll
        for (int dd = 0; dd < 32; dd++) acc += W[i*128 + h*32 + dd] * Rh[dd*32];
        dstW[i*stride + col + jc] = __float2half(acc);
    }
    if (blockIdx.y == 0){
        float accb = 0.f;
        #pragma unroll
        for (int dd = 0; dd < 32; dd++) accb += Bi[h*32 + dd] * Rh[dd*32];
        dstB[col + jc] = accb;
    }
}

// ---------------- merged CSR build ----------------
__global__ void zero_int_kernel(int* __restrict__ p, int n){
    int i = blockIdx.x*blockDim.x + threadIdx.x;
    if (i < n) p[i] = 0;
}
__global__ void hist3_kernel(const int* __restrict__ d0, const int* __restrict__ d1,
                             const int* __restrict__ d2, int* __restrict__ deg){
    int i = blockIdx.x*blockDim.x + threadIdx.x;
    if (i >= 3*NEDGE) return;
    int t = i / NEDGE, e = i - t*NEDGE;
    int d = (t == 0) ? d0[e] : (t == 1) ? d1[e] : d2[e];
    atomicAdd(&deg[t*NP + d], 1);
}
__global__ void partial_kernel(const int* __restrict__ deg, int* __restrict__ part, int n){
    __shared__ int s[256];
    int tid = threadIdx.x;
    int base = blockIdx.x*1024 + tid*4;
    int sum = 0;
    #pragma unroll
    for (int j = 0; j < 4; j++) if (base + j < n) sum += deg[base + j];
    s[tid] = sum; __syncthreads();
    for (int d = 128; d > 0; d >>= 1){
        if (tid < d) s[tid] += s[tid + d];
        __syncthreads();
    }
    if (tid == 0) part[blockIdx.x] = s[0];
}
__global__ void scan_part_kernel(int* __restrict__ part, int nb){
    __shared__ int s[512];
    int tid = threadIdx.x;
    int v = (tid < nb) ? part[tid] : 0;
    s[tid] = v; __syncthreads();
    for (int d = 1; d < 512; d <<= 1){
        int t = (tid >= d) ? s[tid - d] : 0;
        __syncthreads();
        s[tid] += t;
        __syncthreads();
    }
    if (tid < nb) part[tid] = s[tid] - v;
}
__global__ void offsets_kernel(const int* __restrict__ deg, const int* __restrict__ part,
                               int* __restrict__ off, int* __restrict__ cur, int n, int E){
    __shared__ int s[256];
    int tid = threadIdx.x;
    int base = blockIdx.x*1024 + tid*4;
    int v[4];
    #pragma unroll
    for (int j = 0; j < 4; j++) v[j] = (base + j < n) ? deg[base + j] : 0;
    int tsum = v[0]+v[1]+v[2]+v[3];
    s[tid] = tsum; __syncthreads();
    for (int d = 1; d < 256; d <<= 1){
        int t = (tid >= d) ? s[tid - d] : 0;
        __syncthreads();
        s[tid] += t;
        __syncthreads();
    }
    int run = s[tid] - tsum + part[blockIdx.x];
    #pragma unroll
    for (int j = 0; j < 4; j++){
        if (base + j < n){ off[base + j] = run; cur[base + j] = run; }
        run += v[j];
    }
    if (blockIdx.x == 0 && tid == 0) off[n] = E;
}
__global__ void scatter3_kernel(const int* __restrict__ d0, const int* __restrict__ d1,
                                const int* __restrict__ d2, const int* __restrict__ s0,
                                const int* __restrict__ s1, const int* __restrict__ s2,
                                int* __restrict__ cur, int* __restrict__ srcs){
    int i = blockIdx.x*blockDim.x + threadIdx.x;
    if (i >= 3*NEDGE) return;
    int t = i / NEDGE, e = i - t*NEDGE;
    int d  = (t == 0) ? d0[e] : (t == 1) ? d1[e] : d2[e];
    int sv = (t == 0) ? s0[e] : (t == 1) ? s1[e] : s2[e];
    int pos = atomicAdd(&cur[t*NP + d], 1);
    srcs[pos] = sv;
}

// ---------------- single-pass fused attention aggregation ----------------
__device__ __forceinline__ float4 agg_one(int e0, int e1, const int* __restrict__ srcs,
                                          const uint2* __restrict__ buf, int stride4,
                                          int kOff4, int vOff4, float ph, float4 q4, int lane)
{
    float den = 0.f;
    float4 acc = make_float4(0.f,0.f,0.f,0.f);
    for (int base = e0; base < e1; base += 32){
        int m = min(32, e1 - base);
        int myS = (base + lane < e1) ? srcs[base + lane] : 0;
        int j = 0;
        for (; j + 2 <= m; j += 2){
            int sA = __shfl_sync(0xffffffffu, myS, j);
            int sB = __shfl_sync(0xffffffffu, myS, j+1);
            const uint2* rA = buf + (size_t)sA*stride4;
            const uint2* rB = buf + (size_t)sB*stride4;
            float4 kA = h4f(rA[kOff4 + lane]);
            float4 vA = h4f(rA[vOff4 + lane]);
            float4 kB = h4f(rB[kOff4 + lane]);
            float4 vB = h4f(rB[vOff4 + lane]);
            float pA = q4.x*kA.x + q4.y*kA.y + q4.z*kA.z + q4.w*kA.w;
            float pB = q4.x*kB.x + q4.y*kB.y + q4.z*kB.z + q4.w*kB.w;
            pA += __shfl_xor_sync(0xffffffffu, pA, 1);
            pB += __shfl_xor_sync(0xffffffffu, pB, 1);
            pA += __shfl_xor_sync(0xffffffffu, pA, 2);
            pB += __shfl_xor_sync(0xffffffffu, pB, 2);
            pA += __shfl_xor_sync(0xffffffffu, pA, 4);
            pB += __shfl_xor_sync(0xffffffffu, pB, 4);
            float eA = __expf(pA * ph);
            float eB = __expf(pB * ph);
            den += eA + eB;
            acc.x += eA*vA.x + eB*vB.x;
            acc.y += eA*vA.y + eB*vB.y;
            acc.z += eA*vA.z + eB*vB.z;
            acc.w += eA*vA.w + eB*vB.w;
        }
        if (j < m){
            int s = __shfl_sync(0xffffffffu, myS, j);
            const uint2* row = buf + (size_t)s*stride4;
            float4 k4 = h4f(row[kOff4 + lane]);
            float4 v4 = h4f(row[vOff4 + lane]);
            float p = q4.x*k4.x + q4.y*k4.y + q4.z*k4.z + q4.w*k4.w;
            p += __shfl_xor_sync(0xffffffffu, p, 1);
            p += __shfl_xor_sync(0xffffffffu, p, 2);
            p += __shfl_xor_sync(0xffffffffu, p, 4);
            float ex = __expf(p * ph);
            den += ex;
            acc.x += ex*v4.x; acc.y += ex*v4.y;
            acc.z += ex*v4.z; acc.w += ex*v4.w;
        }
    }
    float inv = 1.f/(den + 1e-16f);
    acc.x *= inv; acc.y *= inv; acc.z *= inv; acc.w *= inv;
    return acc;
}

__device__ __forceinline__ void store_h4(__half* dst, float4 v){
    __half2 h0 = __floats2half2_rn(v.x, v.y);
    __half2 h1 = __floats2half2_rn(v.z, v.w);
    uint2 u; u.x = *(unsigned*)&h0; u.y = *(unsigned*)&h1;
    *(uint2*)dst = u;
}

__global__ void aggregate_all(const int* __restrict__ off, const int* __restrict__ srcs,
                              const uint2* __restrict__ actp, const uint2* __restrict__ acta,
                              const float* __restrict__ prel,
                              __half* __restrict__ aggp, __half* __restrict__ agga)
{
    int d = blockIdx.x*8 + (threadIdx.x >> 5);
    int lane = threadIdx.x & 31;
    int h = lane >> 3;
    if (d < NP){
        float4 q4 = h4f(actp[(size_t)d*160 + lane]);
        float ph0 = prel[0*4 + h] * 0.17677669529663687f;
        float ph2 = prel[2*4 + h] * 0.17677669529663687f;
        float4 res = agg_one(off[d], off[d+1], srcs, acta, 96, 32, 64, ph0, q4, lane);
        float4 r2  = agg_one(off[2*NP+d], off[2*NP+d+1], srcs, actp, 160, 96, 128, ph2, q4, lane);
        res.x = gelu_f(0.5f*(res.x + r2.x));
        res.y = gelu_f(0.5f*(res.y + r2.y));
        res.z = gelu_f(0.5f*(res.z + r2.z));
        res.w = gelu_f(0.5f*(res.w + r2.w));
        store_h4(aggp + (size_t)d*128 + lane*4, res);
    } else if (d < NP + NA){
        int da = d - NP;
        float4 q4 = h4f(acta[(size_t)da*96 + lane]);
        float ph1 = prel[1*4 + h] * 0.17677669529663687f;
        float4 res = agg_one(off[NP+da], off[NP+da+1], srcs, actp, 160, 32, 64, ph1, q4, lane);
        res.x = gelu_f(res.x); res.y = gelu_f(res.y);
        res.z = gelu_f(res.z); res.w = gelu_f(res.w);
        store_h4(agga + (size_t)da*128 + lane*4, res);
    }
}

// ---------------- misc ----------------
__global__ void gather_embed_kernel(const float* __restrict__ tab, const int* __restrict__ idx,
                                    __half* __restrict__ out, int n){
    int i = blockIdx.x*blockDim.x + threadIdx.x;
    if (i >= n*32) return;
    int node = i >> 5, c = i & 31;
    int src = idx[node];
    float4 v = ((const float4*)tab)[(size_t)src*32 + c];
    store_h4(out + (size_t)node*128 + c*4, v);
}

// ---------------- launch ----------------
extern "C" void kernel_launch(void* const* d_in, const int* in_sizes, int n_in,
                              void* d_out, int out_size)
{
    const float* x_paper     = (const float*)d_in[0];
    const int*   author_idx  = (const int*)  d_in[1];
    const float* embed_table = (const float*)d_in[2];
    const float* lin_w       = (const float*)d_in[3];
    const float* lin_b       = (const float*)d_in[4];
    const float* k_w         = (const float*)d_in[5];
    const float* k_b         = (const float*)d_in[6];
    const float* q_w         = (const float*)d_in[7];
    const float* q_b         = (const float*)d_in[8];
    const float* v_w         = (const float*)d_in[9];
    const float* v_b         = (const float*)d_in[10];
    const float* a_rel       = (const float*)d_in[11];
    const float* m_rel       = (const float*)d_in[12];
    const float* p_rel       = (const float*)d_in[13];
    const float* skip        = (const float*)d_in[14];
    const float* a_w         = (const float*)d_in[15];
    const float* a_b         = (const float*)d_in[16];
    const int*   w_src       = (const int*)  d_in[17];
    const int*   w_dst       = (const int*)  d_in[18];
    const int*   r_src       = (const int*)  d_in[19];
    const int*   r_dst       = (const int*)  d_in[20];
    const int*   c_src       = (const int*)  d_in[21];
    const int*   c_dst       = (const int*)  d_in[22];
    float* out = (float*)d_out;

    __half *xp,*xa,*actp,*acta,*aggp,*agga,*wlinh;
    __half *wph0,*wah0,*awh0;
    float *bp0,*ba0;
    int *deg,*off,*cur,*srcs,*part;
    cudaGetSymbolAddress((void**)&xp,   g_xp);
    cudaGetSymbolAddress((void**)&xa,   g_xa);
    cudaGetSymbolAddress((void**)&actp, g_actp);
    cudaGetSymbolAddress((void**)&acta, g_acta);
    cudaGetSymbolAddress((void**)&aggp, g_aggp);
    cudaGetSymbolAddress((void**)&agga, g_agga);
    cudaGetSymbolAddress((void**)&wlinh,g_wlinh);
    cudaGetSymbolAddress((void**)&wph0, g_wph);
    cudaGetSymbolAddress((void**)&wah0, g_wah);
    cudaGetSymbolAddress((void**)&awh0, g_awh);
    cudaGetSymbolAddress((void**)&bp0,  g_bp);
    cudaGetSymbolAddress((void**)&ba0,  g_ba);
    cudaGetSymbolAddress((void**)&deg,  g_deg);
    cudaGetSymbolAddress((void**)&off,  g_off);
    cudaGetSymbolAddress((void**)&cur,  g_cur);
    cudaGetSymbolAddress((void**)&srcs, g_srcs);
    cudaGetSymbolAddress((void**)&part, g_part);

    cudaFuncSetAttribute(gemm_mma, cudaFuncAttributeMaxDynamicSharedMemorySize, SMEM_BYTES);

    const int SMB = SMEM_BYTES;
    const int GP = (NP+127)/128, GA = (NA+127)/128;

    prep_weights<<<dim3(21,4),128>>>(k_w, k_b, v_w, v_b, q_w, q_b, a_rel, m_rel, lin_w, a_w);
    gather_embed_kernel<<<(NA*32+255)/256,256>>>(embed_table, author_idx, xa, NA);
    // input projection: X fp32 -> xp fp16
    gemm_mma<<<dim3(GP,1),256,SMB>>>(x_paper, wlinh, 128, lin_b, xp, 128,
                                     nullptr, nullptr, nullptr, 0, NP, 1);

    for (int l = 0; l < 2; l++){
        gemm_mma<<<dim3(GP,5),256,SMB>>>(xp, wph0 + (size_t)l*128*640, 640, bp0 + l*640,
                                         actp, 640, nullptr, nullptr, nullptr, 0, NP, 0);
        gemm_mma<<<dim3(GA,3),256,SMB>>>(xa, wah0 + (size_t)l*128*384, 384, ba0 + l*384,
                                         acta, 384, nullptr, nullptr, nullptr, 0, NA, 0);

        if (l == 0){
            int n = 3*NP;
            int nb = (n + 1023)/1024;
            zero_int_kernel<<<(n+255)/256,256>>>(deg, n);
            hist3_kernel<<<(3*NEDGE+255)/256,256>>>(w_dst, r_dst, c_dst, deg);
            partial_kernel<<<nb,256>>>(deg, part, n);
            scan_part_kernel<<<1,512>>>(part, nb);
            offsets_kernel<<<nb,256>>>(deg, part, off, cur, n, 3*NEDGE);
            scatter3_kernel<<<(3*NEDGE+255)/256,256>>>(w_dst, r_dst, c_dst, w_src, r_src, c_src, cur, srcs);
        }

        aggregate_all<<<(NP+NA+7)/8,256>>>(off, srcs, (const uint2*)actp, (const uint2*)acta,
                                           p_rel + l*12, aggp, agga);

        // update: y = sigmoid(skip)*(acc + b) + (1-sigmoid(skip))*x   (gelu pre-applied in aggregate)
        int mode = (l == 1) ? (2|4|8) : 2;
        gemm_mma<<<dim3(GP,1),256,SMB>>>(aggp, awh0 + (size_t)(l*2+0)*16384, 128, a_b + (l*2+0)*128,
                                         xp, 128, xp, skip + l*2+0,
                                         out, (l==1)?50000:0, NP, mode);
        gemm_mma<<<dim3(GA,1),256,SMB>>>(agga, awh0 + (size_t)(l*2+1)*16384, 128, a_b + (l*2+1)*128,
                                         xa, 128, xa, skip + l*2+1,
                                         out + (size_t)50000*128, (l==1)?25000:0, NA, mode);
    }
}

// round 11
// speedup vs baseline: 4.3646x; 1.0102x over previous
#include <cuda_runtime.h>
#include <cuda_fp16.h>
#include <stdint.h>
#include <math.h>

#define NP 100000
#define NA 50000
#define NEDGE 250000

#define XS2 72                         // X chunk stride (halves): 64 + 8 pad
#define WS2 136                        // W chunk stride (halves): 128 + 8 pad
#define XCH_HALVES (128*XS2)           // 9216
#define WCH_HALVES (64*WS2)            // 8704
#define STAGE_HALVES (XCH_HALVES + WCH_HALVES)   // 17920
#define SMEM_BYTES (2*STAGE_HALVES*2)  // 71680

// ---------------- scratch ----------------
__device__ __half g_xp[(size_t)NP*128];
__device__ __half g_xa[(size_t)NA*128];
__device__ __half g_actp[(size_t)NP*640];   // [q k1 v1 k2 v2]
__device__ __half g_acta[(size_t)NA*384];   // [q k0 v0]
__device__ __half g_aggp[(size_t)NP*128];   // gelu'd, fp16
__device__ __half g_agga[(size_t)NA*128];
__device__ __half g_wph[2][128*640];
__device__ float  g_bp[2][640];
__device__ __half g_wah[2][128*384];
__device__ float  g_ba[2][384];
__device__ __half g_wlinh[128*128];
__device__ __half g_awh[4][128*128];
__device__ int    g_deg[3*NP];
__device__ int    g_off[3*NP+1];
__device__ int    g_cur[3*NP];
__device__ int    g_srcs[3*NEDGE];
__device__ int    g_part[512];

__device__ __forceinline__ float gelu_f(float x){
    return 0.5f*x*(1.0f + erff(x*0.70710678118654752f));
}
__device__ __forceinline__ float4 h4f(uint2 u){
    __half2 a = *(__half2*)&u.x, b = *(__half2*)&u.y;
    float2 fa = __half22float2(a), fb = __half22float2(b);
    return make_float4(fa.x, fa.y, fb.x, fb.y);
}
__device__ __forceinline__ unsigned smem_u32(const void* p){
    unsigned r;
    asm("{ .reg .u64 t; cvta.to.shared.u64 t, %1; cvt.u32.u64 %0, t; }" : "=r"(r) : "l"(p));
    return r;
}
__device__ __forceinline__ void cp_async16(unsigned sa, const void* ga, int sz){
    asm volatile("cp.async.cg.shared.global [%0], [%1], 16, %2;" :: "r"(sa), "l"(ga), "r"(sz));
}
__device__ __forceinline__ void ldmA(unsigned a[4], unsigned addr){
    asm volatile("ldmatrix.sync.aligned.m8n8.x4.shared.b16 {%0,%1,%2,%3}, [%4];"
        : "=r"(a[0]),"=r"(a[1]),"=r"(a[2]),"=r"(a[3]) : "r"(addr));
}
__device__ __forceinline__ void ldmBT(unsigned b[4], unsigned addr){
    asm volatile("ldmatrix.sync.aligned.m8n8.x4.trans.shared.b16 {%0,%1,%2,%3}, [%4];"
        : "=r"(b[0]),"=r"(b[1]),"=r"(b[2]),"=r"(b[3]) : "r"(addr));
}
__device__ __forceinline__ void mma16816(float d[4], const unsigned a[4], const unsigned* b){
    asm volatile("mma.sync.aligned.m16n8k16.row.col.f32.f16.f16.f32 "
        "{%0,%1,%2,%3},{%4,%5,%6,%7},{%8,%9},{%0,%1,%2,%3};"
        : "+f"(d[0]),"+f"(d[1]),"+f"(d[2]),"+f"(d[3])
        : "r"(a[0]),"r"(a[1]),"r"(a[2]),"r"(a[3]),"r"(b[0]),"r"(b[1]));
}

// ---------------- fp16 mma GEMM: [N,128] x [128,Nw], cp.async 2-stage, register epilogue ----------------
// mode bit0: X is fp32 ; bit1: blend y=g*(acc+b)+(1-g)*Xold ; bit2: write out2 fp32 ; bit3: skip Y
__global__ void __launch_bounds__(256, 2)
gemm_mma(const void* __restrict__ Xv, const __half* __restrict__ W, int ldw,
         const float* __restrict__ B, __half* __restrict__ Y, int ldy,
         const __half* __restrict__ Xold, const float* __restrict__ skipPtr,
         float* __restrict__ out2, int out2N,
         int N, int mode)
{
    extern __shared__ __half sh[];
    const int tid = threadIdx.x, warp = tid>>5, lane = tid&31;
    const int wr = warp>>1, wc = warp&1;
    const int bRow = blockIdx.x*128, colBase = blockIdx.y*128;

    __half* Xc0 = sh;
    __half* Wc0 = sh + XCH_HALVES;
    __half* Xc1 = sh + STAGE_HALVES;
    __half* Wc1 = sh + STAGE_HALVES + XCH_HALVES;
    __half* Xc[2] = {Xc0, Xc1};
    __half* Wcb[2] = {Wc0, Wc1};

    const bool async_path = !(mode & 1);

    if (async_path){
        const __half* Xh = (const __half*)Xv;
        #pragma unroll
        for (int c = 0; c < 2; c++){
            #pragma unroll
            for (int i = 0; i < 4; i++){
                int idx = tid + i*256;          // 1024 16B ops: 128 rows x 8
                int r = idx>>3, ch = idx&7;
                int gr = bRow + r;
                unsigned sa = smem_u32(Xc[c] + r*XS2 + ch*8);
                const void* ga = Xh + (size_t)gr*128 + c*64 + ch*8;
                cp_async16(sa, ga, (gr < N) ? 16 : 0);
            }
            #pragma unroll
            for (int i = 0; i < 4; i++){
                int idx = tid + i*256;          // 1024 16B ops: 64 rows x 16
                int r = idx>>4, ch = idx&15;
                unsigned sa = smem_u32(Wcb[c] + r*WS2 + ch*8);
                const void* ga = W + (size_t)(c*64 + r)*ldw + colBase + ch*8;
                cp_async16(sa, ga, 16);
            }
            asm volatile("cp.async.commit_group;");
        }
    } else {
        const float* Xf = (const float*)Xv;
        #pragma unroll
        for (int c = 0; c < 2; c++){
            #pragma unroll
            for (int i = 0; i < 8; i++){
                int idx = tid + i*256;          // 2048 float4: 128 rows x 16
                int r = idx>>4, c4 = idx&15;
                int gr = bRow + r;
                float4 v = (gr < N) ? ((const float4*)Xf)[(size_t)gr*32 + c*16 + c4]
                                    : make_float4(0.f,0.f,0.f,0.f);
                __half2 h0 = __floats2half2_rn(v.x,v.y), h1 = __floats2half2_rn(v.z,v.w);
                uint2 u; u.x = *(unsigned*)&h0; u.y = *(unsigned*)&h1;
                *(uint2*)(Xc[c] + r*XS2 + c4*4) = u;
            }
            #pragma unroll
            for (int i = 0; i < 4; i++){
                int idx = tid + i*256;
                int r = idx>>4, ch = idx&15;
                uint4 v = *(const uint4*)(W + (size_t)(c*64 + r)*ldw + colBase + ch*8);
                *(uint4*)(Wcb[c] + r*WS2 + ch*8) = v;
            }
        }
        __syncthreads();
    }

    float d[2][8][4];
    #pragma unroll
    for (int mi=0;mi<2;mi++)
        #pragma unroll
        for (int ni=0;ni<8;ni++)
            #pragma unroll
            for (int k=0;k<4;k++) d[mi][ni][k]=0.f;

    #pragma unroll
    for (int c = 0; c < 2; c++){
        if (async_path){
            if (c == 0) asm volatile("cp.async.wait_group 1;");
            else        asm volatile("cp.async.wait_group 0;");
            __syncthreads();
        }
        unsigned xA0 = smem_u32(Xc[c]) + (unsigned)(((wr*32 + (lane&15))*XS2 + (lane>>4)*8)*2);
        unsigned xA1 = xA0 + 16*XS2*2;
        unsigned wB  = smem_u32(Wcb[c]) + (unsigned)((((lane&15))*WS2 + wc*64 + (lane>>4)*8)*2);
        #pragma unroll
        for (int ks = 0; ks < 4; ks++){
            unsigned a0[4], a1[4];
            ldmA(a0, xA0 + ks*32);
            ldmA(a1, xA1 + ks*32);
            #pragma unroll
            for (int nt = 0; nt < 4; nt++){
                unsigned bb[4];
                ldmBT(bb, wB + (unsigned)(ks*16*WS2*2) + nt*32);
                mma16816(d[0][2*nt],   a0, bb);
                mma16816(d[0][2*nt+1], a0, bb+2);
                mma16816(d[1][2*nt],   a1, bb);
                mma16816(d[1][2*nt+1], a1, bb+2);
            }
        }
    }

    float gate = 1.f, og = 0.f;
    if (mode & 2){ gate = 1.f/(1.f + expf(-skipPtr[0])); og = 1.f - gate; }
    const int g = lane>>2, t2 = (lane&3)*2;
    float2 bv[8];
    #pragma unroll
    for (int ni=0;ni<8;ni++) bv[ni] = *(const float2*)(B + colBase + wc*64 + ni*8 + t2);

    #pragma unroll
    for (int mi=0;mi<2;mi++){
        int rbase = bRow + wr*32 + mi*16 + g;
        #pragma unroll
        for (int ni=0;ni<8;ni++){
            int c = colBase + wc*64 + ni*8 + t2;
            #pragma unroll
            for (int h=0; h<2; h++){
                int r = rbase + h*8;
                if (r >= N) continue;
                float rx = d[mi][ni][2*h]   + bv[ni].x;
                float ry = d[mi][ni][2*h+1] + bv[ni].y;
                if (mode & 2){
                    __half2 xo = *(const __half2*)(Xold + (size_t)r*128 + c);
                    float2 xf = __half22float2(xo);
                    rx = gate*rx + og*xf.x;
                    ry = gate*ry + og*xf.y;
                }
                if (!(mode & 8)){
                    __half2 hh = __floats2half2_rn(rx, ry);
                    *(__half2*)(Y + (size_t)r*ldy + c) = hh;
                }
                if ((mode & 4) && r < out2N)
                    *(float2*)(out2 + (size_t)r*128 + c) = make_float2(rx, ry);
            }
        }
    }
}

// ---------------- weight prep: fold relation transforms, emit fp16 ----------------
__global__ void prep_weights(const float* __restrict__ k_w, const float* __restrict__ k_b,
                             const float* __restrict__ v_w, const float* __restrict__ v_b,
                             const float* __restrict__ q_w, const float* __restrict__ q_b,
                             const float* __restrict__ a_rel, const float* __restrict__ m_rel,
                             const float* __restrict__ lin_w, const float* __restrict__ a_w)
{
    int fid = blockIdx.x;           // 0..20
    int jc = threadIdx.x;
    int i0 = blockIdx.y * 32;

    if (fid >= 16){
        const float* W = (fid == 16) ? lin_w : a_w + (size_t)(fid-17)*16384;
        __half* D = (fid == 16) ? g_wlinh : g_awh[fid-17];
        for (int i = i0; i < i0+32; i++) D[i*128 + jc] = __float2half(W[i*128 + jc]);
        return;
    }

    int l = fid >> 3, sid = fid & 7;
    bool paper = sid < 5;
    __half* dstW; float* dstB; int stride, col;
    if (paper){ dstW = g_wph[l]; dstB = g_bp[l]; stride = 640; col = sid*128; }
    else      { dstW = g_wah[l]; dstB = g_ba[l]; stride = 384; col = (sid-5)*128; }

    const float *W, *Bi, *R = nullptr;
    switch (sid){
        case 0: W = q_w + (size_t)(l*2+0)*16384; Bi = q_b + (l*2+0)*128; break;
        case 1: W = k_w + (size_t)(l*2+0)*16384; Bi = k_b + (l*2+0)*128; R = a_rel + (size_t)(l*3+1)*4096; break;
        case 2: W = v_w + (size_t)(l*2+0)*16384; Bi = v_b + (l*2+0)*128; R = m_rel + (size_t)(l*3+1)*4096; break;
        case 3: W = k_w + (size_t)(l*2+0)*16384; Bi = k_b + (l*2+0)*128; R = a_rel + (size_t)(l*3+2)*4096; break;
        case 4: W = v_w + (size_t)(l*2+0)*16384; Bi = v_b + (l*2+0)*128; R = m_rel + (size_t)(l*3+2)*4096; break;
        case 5: W = q_w + (size_t)(l*2+1)*16384; Bi = q_b + (l*2+1)*128; break;
        case 6: W = k_w + (size_t)(l*2+1)*16384; Bi = k_b + (l*2+1)*128; R = a_rel + (size_t)(l*3+0)*4096; break;
        default:W = v_w + (size_t)(l*2+1)*16384; Bi = v_b + (l*2+1)*128; R = m_rel + (size_t)(l*3+0)*4096; break;
    }

    if (R == nullptr){
        for (int i = i0; i < i0+32; i++) dstW[i*stride + col + jc] = __float2half(W[i*128 + jc]);
        if (blockIdx.y == 0) dstB[col + jc] = Bi[jc];
        return;
    }
    __shared__ float Rs[4096];
    for (int i = threadIdx.x; i < 4096; i += 128) Rs[i] = R[i];
    __syncthreads();
    int h = jc >> 5, j = jc & 31;
    const float* Rh = Rs + h*1024 + j;
    for (int i = i0; i < i0+32; i++){
        float acc = 0.f;
        #pragma unroll
        for (int dd = 0; dd < 32; dd++) acc += W[i*128 + h*32 + dd] * Rh[dd*32];
        dstW[i*stride + col + jc] = __float2half(acc);
    }
    if (blockIdx.y == 0){
        float accb = 0.f;
        #pragma unroll
        for (int dd = 0; dd < 32; dd++) accb += Bi[h*32 + dd] * Rh[dd*32];
        dstB[col + jc] = accb;
    }
}

// ---------------- merged CSR build ----------------
__global__ void zero_int_kernel(int* __restrict__ p, int n){
    int i = blockIdx.x*blockDim.x + threadIdx.x;
    if (i < n) p[i] = 0;
}
__global__ void hist3_kernel(const int* __restrict__ d0, const int* __restrict__ d1,
                             const int* __restrict__ d2, int* __restrict__ deg){
    int i = blockIdx.x*blockDim.x + threadIdx.x;
    if (i >= 3*NEDGE) return;
    int t = i / NEDGE, e = i - t*NEDGE;
    int d = (t == 0) ? d0[e] : (t == 1) ? d1[e] : d2[e];
    atomicAdd(&deg[t*NP + d], 1);
}
__global__ void partial_kernel(const int* __restrict__ deg, int* __restrict__ part, int n){
    __shared__ int s[256];
    int tid = threadIdx.x;
    int base = blockIdx.x*1024 + tid*4;
    int sum = 0;
    #pragma unroll
    for (int j = 0; j < 4; j++) if (base + j < n) sum += deg[base + j];
    s[tid] = sum; __syncthreads();
    for (int d = 128; d > 0; d >>= 1){
        if (tid < d) s[tid] += s[tid + d];
        __syncthreads();
    }
    if (tid == 0) part[blockIdx.x] = s[0];
}
__global__ void scan_part_kernel(int* __restrict__ part, int nb){
    __shared__ int s[512];
    int tid = threadIdx.x;
    int v = (tid < nb) ? part[tid] : 0;
    s[tid] = v; __syncthreads();
    for (int d = 1; d < 512; d <<= 1){
        int t = (tid >= d) ? s[tid - d] : 0;
        __syncthreads();
        s[tid] += t;
        __syncthreads();
    }
    if (tid < nb) part[tid] = s[tid] - v;
}
__global__ void offsets_kernel(const int* __restrict__ deg, const int* __restrict__ part,
                               int* __restrict__ off, int* __restrict__ cur, int n, int E){
    __shared__ int s[256];
    int tid = threadIdx.x;
    int base = blockIdx.x*1024 + tid*4;
    int v[4];
    #pragma unroll
    for (int j = 0; j < 4; j++) v[j] = (base + j < n) ? deg[base + j] : 0;
    int tsum = v[0]+v[1]+v[2]+v[3];
    s[tid] = tsum; __syncthreads();
    for (int d = 1; d < 256; d <<= 1){
        int t = (tid >= d) ? s[tid - d] : 0;
        __syncthreads();
        s[tid] += t;
        __syncthreads();
    }
    int run = s[tid] - tsum + part[blockIdx.x];
    #pragma unroll
    for (int j = 0; j < 4; j++){
        if (base + j < n){ off[base + j] = run; cur[base + j] = run; }
        run += v[j];
    }
    if (blockIdx.x == 0 && tid == 0) off[n] = E;
}
__global__ void scatter3_kernel(const int* __restrict__ d0, const int* __restrict__ d1,
                                const int* __restrict__ d2, const int* __restrict__ s0,
                                const int* __restrict__ s1, const int* __restrict__ s2,
                                int* __restrict__ cur, int* __restrict__ srcs){
    int i = blockIdx.x*blockDim.x + threadIdx.x;
    if (i >= 3*NEDGE) return;
    int t = i / NEDGE, e = i - t*NEDGE;
    int d  = (t == 0) ? d0[e] : (t == 1) ? d1[e] : d2[e];
    int sv = (t == 0) ? s0[e] : (t == 1) ? s1[e] : s2[e];
    int pos = atomicAdd(&cur[t*NP + d], 1);
    srcs[pos] = sv;
}

// ---------------- single-pass fused attention aggregation (4-wide MLP) ----------------
__device__ __forceinline__ float4 agg_one(int e0, int e1, const int* __restrict__ srcs,
                                          const uint2* __restrict__ buf, int stride4,
                                          int kOff4, int vOff4, float ph, float4 q4, int lane)
{
    float den = 0.f;
    float4 acc = make_float4(0.f,0.f,0.f,0.f);
    for (int base = e0; base < e1; base += 32){
        int m = min(32, e1 - base);
        int myS = (base + lane < e1) ? srcs[base + lane] : 0;
        int j = 0;
        for (; j + 4 <= m; j += 4){
            int s0 = __shfl_sync(0xffffffffu, myS, j);
            int s1 = __shfl_sync(0xffffffffu, myS, j+1);
            int s2 = __shfl_sync(0xffffffffu, myS, j+2);
            int s3 = __shfl_sync(0xffffffffu, myS, j+3);
            const uint2* r0 = buf + (size_t)s0*stride4;
            const uint2* r1 = buf + (size_t)s1*stride4;
            const uint2* r2 = buf + (size_t)s2*stride4;
            const uint2* r3 = buf + (size_t)s3*stride4;
            uint2 k0u = r0[kOff4 + lane], v0u = r0[vOff4 + lane];
            uint2 k1u = r1[kOff4 + lane], v1u = r1[vOff4 + lane];
            uint2 k2u = r2[kOff4 + lane], v2u = r2[vOff4 + lane];
            uint2 k3u = r3[kOff4 + lane], v3u = r3[vOff4 + lane];
            float4 k0 = h4f(k0u), k1 = h4f(k1u), k2 = h4f(k2u), k3 = h4f(k3u);
            float p0 = q4.x*k0.x + q4.y*k0.y + q4.z*k0.z + q4.w*k0.w;
            float p1 = q4.x*k1.x + q4.y*k1.y + q4.z*k1.z + q4.w*k1.w;
            float p2 = q4.x*k2.x + q4.y*k2.y + q4.z*k2.z + q4.w*k2.w;
            float p3 = q4.x*k3.x + q4.y*k3.y + q4.z*k3.z + q4.w*k3.w;
            p0 += __shfl_xor_sync(0xffffffffu, p0, 1);
            p1 += __shfl_xor_sync(0xffffffffu, p1, 1);
            p2 += __shfl_xor_sync(0xffffffffu, p2, 1);
            p3 += __shfl_xor_sync(0xffffffffu, p3, 1);
            p0 += __shfl_xor_sync(0xffffffffu, p0, 2);
            p1 += __shfl_xor_sync(0xffffffffu, p1, 2);
            p2 += __shfl_xor_sync(0xffffffffu, p2, 2);
            p3 += __shfl_xor_sync(0xffffffffu, p3, 2);
            p0 += __shfl_xor_sync(0xffffffffu, p0, 4);
            p1 += __shfl_xor_sync(0xffffffffu, p1, 4);
            p2 += __shfl_xor_sync(0xffffffffu, p2, 4);
            p3 += __shfl_xor_sync(0xffffffffu, p3, 4);
            float e0f = __expf(p0 * ph), e1f = __expf(p1 * ph);
            float e2f = __expf(p2 * ph), e3f = __expf(p3 * ph);
            den += (e0f + e1f) + (e2f + e3f);
            float4 v0 = h4f(v0u), v1 = h4f(v1u), v2 = h4f(v2u), v3 = h4f(v3u);
            acc.x += e0f*v0.x + e1f*v1.x + e2f*v2.x + e3f*v3.x;
            acc.y += e0f*v0.y + e1f*v1.y + e2f*v2.y + e3f*v3.y;
            acc.z += e0f*v0.z + e1f*v1.z + e2f*v2.z + e3f*v3.z;
            acc.w += e0f*v0.w + e1f*v1.w + e2f*v2.w + e3f*v3.w;
        }
        for (; j < m; j++){
            int s = __shfl_sync(0xffffffffu, myS, j);
            const uint2* row = buf + (size_t)s*stride4;
            float4 k4 = h4f(row[kOff4 + lane]);
            float4 v4 = h4f(row[vOff4 + lane]);
            float p = q4.x*k4.x + q4.y*k4.y + q4.z*k4.z + q4.w*k4.w;
            p += __shfl_xor_sync(0xffffffffu, p, 1);
            p += __shfl_xor_sync(0xffffffffu, p, 2);
            p += __shfl_xor_sync(0xffffffffu, p, 4);
            float ex = __expf(p * ph);
            den += ex;
            acc.x += ex*v4.x; acc.y += ex*v4.y;
            acc.z += ex*v4.z; acc.w += ex*v4.w;
        }
    }
    float inv = 1.f/(den + 1e-16f);
    acc.x *= inv; acc.y *= inv; acc.z *= inv; acc.w *= inv;
    return acc;
}

__device__ __forceinline__ void store_h4(__half* dst, float4 v){
    __half2 h0 = __floats2half2_rn(v.x, v.y);
    __half2 h1 = __floats2half2_rn(v.z, v.w);
    uint2 u; u.x = *(unsigned*)&h0; u.y = *(unsigned*)&h1;
    *(uint2*)dst = u;
}

__global__ void aggregate_all(const int* __restrict__ off, const int* __restrict__ srcs,
                              const uint2* __restrict__ actp, const uint2* __restrict__ acta,
                              const float* __restrict__ prel,
                              __half* __restrict__ aggp, __half* __restrict__ agga)
{
    int d = blockIdx.x*8 + (threadIdx.x >> 5);
    int lane = threadIdx.x & 31;
    int h = lane >> 3;
    if (d < NP){
        float4 q4 = h4f(actp[(size_t)d*160 + lane]);
        float ph0 = prel[0*4 + h] * 0.17677669529663687f;
        float ph2 = prel[2*4 + h] * 0.17677669529663687f;
        float4 res = agg_one(off[d], off[d+1], srcs, acta, 96, 32, 64, ph0, q4, lane);
        float4 r2  = agg_one(off[2*NP+d], off[2*NP+d+1], srcs, actp, 160, 96, 128, ph2, q4, lane);
        res.x = gelu_f(0.5f*(res.x + r2.x));
        res.y = gelu_f(0.5f*(res.y + r2.y));
        res.z = gelu_f(0.5f*(res.z + r2.z));
        res.w = gelu_f(0.5f*(res.w + r2.w));
        store_h4(aggp + (size_t)d*128 + lane*4, res);
    } else if (d < NP + NA){
        int da = d - NP;
        float4 q4 = h4f(acta[(size_t)da*96 + lane]);
        float ph1 = prel[1*4 + h] * 0.17677669529663687f;
        float4 res = agg_one(off[NP+da], off[NP+da+1], srcs, actp, 160, 32, 64, ph1, q4, lane);
        res.x = gelu_f(res.x); res.y = gelu_f(res.y);
        res.z = gelu_f(res.z); res.w = gelu_f(res.w);
        store_h4(agga + (size_t)da*128 + lane*4, res);
    }
}

// ---------------- misc ----------------
__global__ void gather_embed_kernel(const float* __restrict__ tab, const int* __restrict__ idx,
                                    __half* __restrict__ out, int n){
    int i = blockIdx.x*blockDim.x + threadIdx.x;
    if (i >= n*32) return;
    int node = i >> 5, c = i & 31;
    int src = idx[node];
    float4 v = ((const float4*)tab)[(size_t)src*32 + c];
    store_h4(out + (size_t)node*128 + c*4, v);
}

// ---------------- launch ----------------
extern "C" void kernel_launch(void* const* d_in, const int* in_sizes, int n_in,
                              void* d_out, int out_size)
{
    const float* x_paper     = (const float*)d_in[0];
    const int*   author_idx  = (const int*)  d_in[1];
    const float* embed_table = (const float*)d_in[2];
    const float* lin_w       = (const float*)d_in[3];
    const float* lin_b       = (const float*)d_in[4];
    const float* k_w         = (const float*)d_in[5];
    const float* k_b         = (const float*)d_in[6];
    const float* q_w         = (const float*)d_in[7];
    const float* q_b         = (const float*)d_in[8];
    const float* v_w         = (const float*)d_in[9];
    const float* v_b         = (const float*)d_in[10];
    const float* a_rel       = (const float*)d_in[11];
    const float* m_rel       = (const float*)d_in[12];
    const float* p_rel       = (const float*)d_in[13];
    const float* skip        = (const float*)d_in[14];
    const float* a_w         = (const float*)d_in[15];
    const float* a_b         = (const float*)d_in[16];
    const int*   w_src       = (const int*)  d_in[17];
    const int*   w_dst       = (const int*)  d_in[18];
    const int*   r_src       = (const int*)  d_in[19];
    const int*   r_dst       = (const int*)  d_in[20];
    const int*   c_src       = (const int*)  d_in[21];
    const int*   c_dst       = (const int*)  d_in[22];
    float* out = (float*)d_out;

    __half *xp,*xa,*actp,*acta,*aggp,*agga,*wlinh;
    __half *wph0,*wah0,*awh0;
    float *bp0,*ba0;
    int *deg,*off,*cur,*srcs,*part;
    cudaGetSymbolAddress((void**)&xp,   g_xp);
    cudaGetSymbolAddress((void**)&xa,   g_xa);
    cudaGetSymbolAddress((void**)&actp, g_actp);
    cudaGetSymbolAddress((void**)&acta, g_acta);
    cudaGetSymbolAddress((void**)&aggp, g_aggp);
    cudaGetSymbolAddress((void**)&agga, g_agga);
    cudaGetSymbolAddress((void**)&wlinh,g_wlinh);
    cudaGetSymbolAddress((void**)&wph0, g_wph);
    cudaGetSymbolAddress((void**)&wah0, g_wah);
    cudaGetSymbolAddress((void**)&awh0, g_awh);
    cudaGetSymbolAddress((void**)&bp0,  g_bp);
    cudaGetSymbolAddress((void**)&ba0,  g_ba);
    cudaGetSymbolAddress((void**)&deg,  g_deg);
    cudaGetSymbolAddress((void**)&off,  g_off);
    cudaGetSymbolAddress((void**)&cur,  g_cur);
    cudaGetSymbolAddress((void**)&srcs, g_srcs);
    cudaGetSymbolAddress((void**)&part, g_part);

    cudaFuncSetAttribute(gemm_mma, cudaFuncAttributeMaxDynamicSharedMemorySize, SMEM_BYTES);

    const int SMB = SMEM_BYTES;
    const int GP = (NP+127)/128, GA = (NA+127)/128;

    prep_weights<<<dim3(21,4),128>>>(k_w, k_b, v_w, v_b, q_w, q_b, a_rel, m_rel, lin_w, a_w);
    gather_embed_kernel<<<(NA*32+255)/256,256>>>(embed_table, author_idx, xa, NA);
    // input projection: X fp32 -> xp fp16 (sync path)
    gemm_mma<<<dim3(GP,1),256,SMB>>>(x_paper, wlinh, 128, lin_b, xp, 128,
                                     nullptr, nullptr, nullptr, 0, NP, 1);

    for (int l = 0; l < 2; l++){
        gemm_mma<<<dim3(GP,5),256,SMB>>>(xp, wph0 + (size_t)l*128*640, 640, bp0 + l*640,
                                         actp, 640, nullptr, nullptr, nullptr, 0, NP, 0);
        gemm_mma<<<dim3(GA,3),256,SMB>>>(xa, wah0 + (size_t)l*128*384, 384, ba0 + l*384,
                                         acta, 384, nullptr, nullptr, nullptr, 0, NA, 0);

        if (l == 0){
            int n = 3*NP;
            int nb = (n + 1023)/1024;
            zero_int_kernel<<<(n+255)/256,256>>>(deg, n);
            hist3_kernel<<<(3*NEDGE+255)/256,256>>>(w_dst, r_dst, c_dst, deg);
            partial_kernel<<<nb,256>>>(deg, part, n);
            scan_part_kernel<<<1,512>>>(part, nb);
            offsets_kernel<<<nb,256>>>(deg, part, off, cur, n, 3*NEDGE);
            scatter3_kernel<<<(3*NEDGE+255)/256,256>>>(w_dst, r_dst, c_dst, w_src, r_src, c_src, cur, srcs);
        }

        aggregate_all<<<(NP+NA+7)/8,256>>>(off, srcs, (const uint2*)actp, (const uint2*)acta,
                                           p_rel + l*12, aggp, agga);

        // update: y = sigmoid(skip)*(acc + b) + (1-sigmoid(skip))*x   (gelu pre-applied in aggregate)
        int mode = (l == 1) ? (2|4|8) : 2;
        gemm_mma<<<dim3(GP,1),256,SMB>>>(aggp, awh0 + (size_t)(l*2+0)*16384, 128, a_b + (l*2+0)*128,
                                         xp, 128, xp, skip + l*2+0,
                                         out, (l==1)?50000:0, NP, mode);
        gemm_mma<<<dim3(GA,1),256,SMB>>>(agga, awh0 + (size_t)(l*2+1)*16384, 128, a_b + (l*2+1)*128,
                                         xa, 128, xa, skip + l*2+1,
                                         out + (size_t)50000*128, (l==1)?25000:0, NA, mode);
    }
}